// round 1
// baseline (speedup 1.0000x reference)
#include <cuda_runtime.h>

// ---------------------------------------------------------------------------
// HeteroGNN (3-layer hetero SAGE) on GB300.
// Round 1: correct fp32 baseline.
//   - deg/inv precompute (per launch), atomic scatter-mean aggregation
//   - fused GEMM: out = (agg*inv) @ Wl + relu?(x_dst) @ Wr + b, row-L2-norm,
//     accumulate across edge types (HeteroConv sum), lazy ReLU on reads
//   - layer 2 computes only edge types feeding 'reaction'
//   - inner product uses packed fma.rn.f32x2 (FFMA2) for 2x fp32 throughput
// ---------------------------------------------------------------------------

#define DIM 256

static const int  NNODE[4]  = {100000, 50000, 200000, 150000}; // reaction, complex, protein, molecule
static const long XOFF[4]   = {0, 100000, 150000, 350000};     // row offsets in x buffers
static const int  ET_S[7]   = {2, 3, 1, 2, 3, 0, 0};
static const int  ET_D[7]   = {0, 0, 0, 1, 1, 2, 3};
static const long DEGOFF[7] = {0, 100000, 200000, 300000, 350000, 400000, 600000};
#define DEG_TOTAL 750000
#define N_EDGE 300000

// scratch (device globals: no cudaMalloc allowed)
__device__ float g_xA[128000000];   // 500k rows x 256
__device__ float g_xB[128000000];
__device__ float g_agg[51200000];   // max 200k rows x 256
__device__ float g_inv[DEG_TOTAL];
__device__ int   g_deg[DEG_TOTAL];

// ---- packed f32x2 helpers (FFMA2 path, sm_103a) ----------------------------
#define PACK2(out, lo, hi) \
    asm("mov.b64 %0, {%1, %2};" : "=l"(out) : "r"(__float_as_uint(lo)), "r"(__float_as_uint(hi)))
#define FMA2(acc, a, b) \
    asm("fma.rn.f32x2 %0, %1, %2, %0;" : "+l"(acc) : "l"(a), "l"(b))
#define UNPACK2(lo, hi, in) do { \
    unsigned _ul, _uh; \
    asm("mov.b64 {%0, %1}, %2;" : "=r"(_ul), "=r"(_uh) : "l"(in)); \
    lo = __uint_as_float(_ul); hi = __uint_as_float(_uh); } while (0)

__device__ __forceinline__ const float* resolve_x(const float* ext, int sel, long rowoff) {
    if (sel == 0) return g_xA + rowoff * DIM;
    if (sel == 1) return g_xB + rowoff * DIM;
    return ext;
}

// ---- small utility kernels --------------------------------------------------
__global__ void bcast_init(const float* __restrict__ remb, const float* __restrict__ cemb) {
    long row = blockIdx.x;                       // 0..149999
    const float4* src = (const float4*)(row < 100000 ? remb : cemb);
    float4* dst = (float4*)(g_xA + row * DIM);
    dst[threadIdx.x] = src[threadIdx.x];         // 64 threads * float4
}

__global__ void zero_deg_kernel() {
    int i = blockIdx.x * blockDim.x + threadIdx.x;
    if (i < DEG_TOTAL) g_deg[i] = 0;
}

__global__ void deg_kernel(const int* __restrict__ dstIdx, int e, long degOff) {
    int i = blockIdx.x * blockDim.x + threadIdx.x;
    if (i < e) atomicAdd(&g_deg[degOff + dstIdx[i]], 1);
}

__global__ void inv_kernel() {
    int i = blockIdx.x * blockDim.x + threadIdx.x;
    if (i < DEG_TOTAL) g_inv[i] = 1.0f / fmaxf((float)g_deg[i], 1.0f);
}

__global__ void zero_agg_kernel(long n4) {
    long i = (long)blockIdx.x * blockDim.x + threadIdx.x;
    if (i < n4) ((float4*)g_agg)[i] = make_float4(0.f, 0.f, 0.f, 0.f);
}

// ---- scatter: warp per edge, atomic row add into g_agg ----------------------
__global__ void scatter_kernel(const float* __restrict__ ext, int sel, long rowoff,
                               const int* __restrict__ srcIdx,
                               const int* __restrict__ dstIdx,
                               int e, int relu) {
    int g = blockIdx.x * blockDim.x + threadIdx.x;
    int w = g >> 5;
    if (w >= e) return;
    int lane = g & 31;
    const float* X = resolve_x(ext, sel, rowoff);
    long s = srcIdx[w];
    long d = dstIdx[w];
    const float4* a = (const float4*)(X + s * DIM);
    float4 v0 = a[lane];
    float4 v1 = a[lane + 32];
    if (relu) {
        v0.x = fmaxf(v0.x, 0.f); v0.y = fmaxf(v0.y, 0.f);
        v0.z = fmaxf(v0.z, 0.f); v0.w = fmaxf(v0.w, 0.f);
        v1.x = fmaxf(v1.x, 0.f); v1.y = fmaxf(v1.y, 0.f);
        v1.z = fmaxf(v1.z, 0.f); v1.w = fmaxf(v1.w, 0.f);
    }
    float* o = g_agg + d * DIM;
    atomicAdd(&o[lane * 4 + 0], v0.x);
    atomicAdd(&o[lane * 4 + 1], v0.y);
    atomicAdd(&o[lane * 4 + 2], v0.z);
    atomicAdd(&o[lane * 4 + 3], v0.w);
    atomicAdd(&o[128 + lane * 4 + 0], v1.x);
    atomicAdd(&o[128 + lane * 4 + 1], v1.y);
    atomicAdd(&o[128 + lane * 4 + 2], v1.z);
    atomicAdd(&o[128 + lane * 4 + 3], v1.w);
}

// ---- fused SAGE GEMM: (agg*inv)@Wl + relu?(x_dst)@Wr + b, row L2 norm, acc --
// BM=64, BN=256 (full row per block), BK=16, 256 threads, 8x8 per thread.
__global__ __launch_bounds__(256, 2) void sage_gemm(
    const float* __restrict__ A2ext, int a2sel, long a2off,
    const float* __restrict__ Bl, const float* __restrict__ Br,
    const float* __restrict__ bias,
    int outsel, long outoff, long invoff,
    int n, int accum, int reluA2) {
    __shared__ float As[16][64];
    __shared__ float Bs[16][256];

    const int tid = threadIdx.x;
    const long row0 = (long)blockIdx.x * 64;
    const int m = tid & 63, kq = tid >> 6;     // A load
    const int jb = tid & 63, kb = tid >> 6;    // B load
    const int tcol = tid & 31, tr = tid >> 5;  // compute

    const float* A2 = resolve_x(A2ext, a2sel, a2off);
    float* Out = ((outsel == 0) ? g_xA : g_xB) + outoff * DIM;

    unsigned long long acc[8][4];
#pragma unroll
    for (int i = 0; i < 8; i++)
#pragma unroll
        for (int p = 0; p < 4; p++) acc[i][p] = 0ULL;

    const long arow = row0 + m;
    const bool aval = arow < n;
    const float invm = aval ? g_inv[invoff + arow] : 0.f;

#pragma unroll 1
    for (int ph = 0; ph < 2; ++ph) {
        const float* Ag = ph ? A2 : g_agg;
        const float* Bg = ph ? Br : Bl;
#pragma unroll 1
        for (int k0 = 0; k0 < 256; k0 += 16) {
            float4 av = make_float4(0.f, 0.f, 0.f, 0.f);
            if (aval) av = *(const float4*)&Ag[arow * DIM + k0 + kq * 4];
            if (ph == 0) {
                av.x *= invm; av.y *= invm; av.z *= invm; av.w *= invm;
            } else if (reluA2) {
                av.x = fmaxf(av.x, 0.f); av.y = fmaxf(av.y, 0.f);
                av.z = fmaxf(av.z, 0.f); av.w = fmaxf(av.w, 0.f);
            }
            float4 bv[4];
#pragma unroll
            for (int r = 0; r < 4; r++)
                bv[r] = *(const float4*)&Bg[(long)(k0 + kb + r * 4) * DIM + jb * 4];
            __syncthreads();
            As[kq * 4 + 0][m] = av.x;
            As[kq * 4 + 1][m] = av.y;
            As[kq * 4 + 2][m] = av.z;
            As[kq * 4 + 3][m] = av.w;
#pragma unroll
            for (int r = 0; r < 4; r++)
                *(float4*)&Bs[kb + r * 4][jb * 4] = bv[r];
            __syncthreads();
#pragma unroll
            for (int k = 0; k < 16; k++) {
                ulonglong2 b01 = *(const ulonglong2*)&Bs[k][tcol * 4];
                ulonglong2 b23 = *(const ulonglong2*)&Bs[k][128 + tcol * 4];
                float4 a0 = *(const float4*)&As[k][tr * 8];
                float4 a1 = *(const float4*)&As[k][tr * 8 + 4];
                float aa[8] = {a0.x, a0.y, a0.z, a0.w, a1.x, a1.y, a1.z, a1.w};
#pragma unroll
                for (int i = 0; i < 8; i++) {
                    unsigned long long a2v;
                    PACK2(a2v, aa[i], aa[i]);
                    FMA2(acc[i][0], a2v, b01.x);
                    FMA2(acc[i][1], a2v, b01.y);
                    FMA2(acc[i][2], a2v, b23.x);
                    FMA2(acc[i][3], a2v, b23.y);
                }
            }
        }
    }

    // epilogue: +bias, row L2 norm (warp owns 8 full rows), accumulate store
    float4 bb0 = *(const float4*)&bias[tcol * 4];
    float4 bb1 = *(const float4*)&bias[128 + tcol * 4];
    float bsv[8] = {bb0.x, bb0.y, bb0.z, bb0.w, bb1.x, bb1.y, bb1.z, bb1.w};

#pragma unroll
    for (int i = 0; i < 8; i++) {
        float v[8];
        UNPACK2(v[0], v[1], acc[i][0]);
        UNPACK2(v[2], v[3], acc[i][1]);
        UNPACK2(v[4], v[5], acc[i][2]);
        UNPACK2(v[6], v[7], acc[i][3]);
        float ss = 0.f;
#pragma unroll
        for (int q = 0; q < 8; q++) { v[q] += bsv[q]; ss += v[q] * v[q]; }
#pragma unroll
        for (int o = 16; o > 0; o >>= 1) ss += __shfl_xor_sync(0xffffffffu, ss, o);
        float sc = 1.0f / fmaxf(sqrtf(ss), 1e-12f);
        long r = row0 + (long)tr * 8 + i;
        if (r < n) {
            float4 o0 = make_float4(v[0] * sc, v[1] * sc, v[2] * sc, v[3] * sc);
            float4 o1 = make_float4(v[4] * sc, v[5] * sc, v[6] * sc, v[7] * sc);
            float* op = Out + r * DIM;
            if (accum) {
                float4 u0 = *(float4*)&op[tcol * 4];
                float4 u1 = *(float4*)&op[128 + tcol * 4];
                o0.x += u0.x; o0.y += u0.y; o0.z += u0.z; o0.w += u0.w;
                o1.x += u1.x; o1.y += u1.y; o1.z += u1.z; o1.w += u1.w;
            }
            *(float4*)&op[tcol * 4] = o0;
            *(float4*)&op[128 + tcol * 4] = o1;
        }
    }
}

// ---- final head: relu(x_reaction) @ W_out[256x128] + b_out ------------------
__global__ __launch_bounds__(256, 2) void final_gemm(
    int asel, long aoff, const float* __restrict__ W,
    const float* __restrict__ bias, float* __restrict__ C, int n) {
    __shared__ float As[16][64];
    __shared__ float Bs[16][128];
    const int tid = threadIdx.x;
    const long row0 = (long)blockIdx.x * 64;
    const int m = tid & 63, kq = tid >> 6;
    const int jb = tid & 31, kb2 = tid >> 5;
    const int tcol = tid & 31, tr = tid >> 5;

    const float* A = resolve_x(nullptr, asel, aoff);

    unsigned long long acc[8][2];
#pragma unroll
    for (int i = 0; i < 8; i++) { acc[i][0] = 0ULL; acc[i][1] = 0ULL; }

    const long arow = row0 + m;
    const bool aval = arow < n;

#pragma unroll 1
    for (int k0 = 0; k0 < 256; k0 += 16) {
        float4 av = make_float4(0.f, 0.f, 0.f, 0.f);
        if (aval) av = *(const float4*)&A[arow * DIM + k0 + kq * 4];
        av.x = fmaxf(av.x, 0.f); av.y = fmaxf(av.y, 0.f);
        av.z = fmaxf(av.z, 0.f); av.w = fmaxf(av.w, 0.f);
        float4 bv0 = *(const float4*)&W[(long)(k0 + kb2) * 128 + jb * 4];
        float4 bv1 = *(const float4*)&W[(long)(k0 + kb2 + 8) * 128 + jb * 4];
        __syncthreads();
        As[kq * 4 + 0][m] = av.x;
        As[kq * 4 + 1][m] = av.y;
        As[kq * 4 + 2][m] = av.z;
        As[kq * 4 + 3][m] = av.w;
        *(float4*)&Bs[kb2][jb * 4] = bv0;
        *(float4*)&Bs[kb2 + 8][jb * 4] = bv1;
        __syncthreads();
#pragma unroll
        for (int k = 0; k < 16; k++) {
            ulonglong2 b01 = *(const ulonglong2*)&Bs[k][tcol * 4];
            float4 a0 = *(const float4*)&As[k][tr * 8];
            float4 a1 = *(const float4*)&As[k][tr * 8 + 4];
            float aa[8] = {a0.x, a0.y, a0.z, a0.w, a1.x, a1.y, a1.z, a1.w};
#pragma unroll
            for (int i = 0; i < 8; i++) {
                unsigned long long a2v;
                PACK2(a2v, aa[i], aa[i]);
                FMA2(acc[i][0], a2v, b01.x);
                FMA2(acc[i][1], a2v, b01.y);
            }
        }
    }

    float4 bb = *(const float4*)&bias[tcol * 4];
    float bsv[4] = {bb.x, bb.y, bb.z, bb.w};
#pragma unroll
    for (int i = 0; i < 8; i++) {
        float v[4];
        UNPACK2(v[0], v[1], acc[i][0]);
        UNPACK2(v[2], v[3], acc[i][1]);
        long r = row0 + (long)tr * 8 + i;
        if (r < n) {
            float4 o0 = make_float4(v[0] + bsv[0], v[1] + bsv[1],
                                    v[2] + bsv[2], v[3] + bsv[3]);
            *(float4*)&C[r * 128 + tcol * 4] = o0;
        }
    }
}

// ---------------------------------------------------------------------------
extern "C" void kernel_launch(void* const* d_in, const int* in_sizes, int n_in,
                              void* d_out, int out_size) {
    const float* remb = (const float*)d_in[4];
    const float* cemb = (const float*)d_in[5];
    const float* ptab = (const float*)d_in[6];
    const float* mtab = (const float*)d_in[7];
    const float* Wl   = (const float*)d_in[8];
    const float* Wr   = (const float*)d_in[9];
    const float* bvec = (const float*)d_in[10];
    const float* Wout = (const float*)d_in[11];
    const float* bout = (const float*)d_in[12];
    const int* edge[7];
    int ecnt[7];
    for (int t = 0; t < 7; t++) {
        edge[t] = (const int*)d_in[13 + t];
        ecnt[t] = in_sizes[13 + t] / 2;   // [2, E]
    }

    // layer-0 features: broadcast reaction/complex rows into g_xA
    bcast_init<<<150000, 64>>>(remb, cemb);

    // degrees (constant across layers) -> inv = 1/max(deg,1)
    zero_deg_kernel<<<(DEG_TOTAL + 255) / 256, 256>>>();
    for (int t = 0; t < 7; t++)
        deg_kernel<<<(ecnt[t] + 255) / 256, 256>>>(edge[t] + ecnt[t], ecnt[t], DEGOFF[t]);
    inv_kernel<<<(DEG_TOTAL + 255) / 256, 256>>>();

    for (int l = 0; l < 3; l++) {
        // source/dest feature descriptors for this layer
        int xs_sel[4]; long xs_off[4]; const float* xs_ext[4];
        if (l == 0) {
            xs_sel[0] = 0; xs_off[0] = XOFF[0]; xs_ext[0] = nullptr;   // reaction in g_xA
            xs_sel[1] = 0; xs_off[1] = XOFF[1]; xs_ext[1] = nullptr;   // complex in g_xA
            xs_sel[2] = 2; xs_off[2] = 0;       xs_ext[2] = ptab;      // protein table
            xs_sel[3] = 2; xs_off[3] = 0;       xs_ext[3] = mtab;      // molecule table
        } else {
            int sel = (l == 1) ? 1 : 0;   // l1 reads xB, l2 reads xA
            for (int k = 0; k < 4; k++) { xs_sel[k] = sel; xs_off[k] = XOFF[k]; xs_ext[k] = nullptr; }
        }
        int osel = (l == 1) ? 0 : 1;      // l0->xB, l1->xA, l2->xB
        int ntypes = (l == 2) ? 3 : 7;    // last layer: only dst 'reaction' matters
        int relu = (l > 0) ? 1 : 0;
        bool first[4] = {true, true, true, true};

        for (int t = 0; t < ntypes; t++) {
            int s = ET_S[t], d = ET_D[t];
            int nd = NNODE[d];
            long n4 = (long)nd * 64;
            zero_agg_kernel<<<(int)((n4 + 255) / 256), 256>>>(n4);
            int e = ecnt[t];
            scatter_kernel<<<(e * 32 + 255) / 256, 256>>>(
                xs_ext[s], xs_sel[s], xs_off[s], edge[t], edge[t] + e, e, relu);
            sage_gemm<<<(nd + 63) / 64, 256>>>(
                xs_ext[d], xs_sel[d], xs_off[d],
                Wl + (long)(l * 7 + t) * 65536,
                Wr + (long)(l * 7 + t) * 65536,
                bvec + (long)(l * 7 + t) * 256,
                osel, XOFF[d], DEGOFF[t],
                nd, first[d] ? 0 : 1, relu);
            first[d] = false;
        }
    }

    // head: relu(x_reaction layer-2, in g_xB) @ W_out + b_out
    final_gemm<<<(NNODE[0] + 63) / 64, 256>>>(1, XOFF[0], Wout, bout,
                                              (float*)d_out, NNODE[0]);
}

// round 2
// speedup vs baseline: 2.2516x; 2.2516x over previous
#include <cuda_runtime.h>

// ---------------------------------------------------------------------------
// HeteroGNN (3-layer hetero SAGE) on GB300 — Round 2.
//   R2 changes vs R1:
//   - layer-0 rank-1 algebra: broadcast reaction/complex embeddings mean that
//     5 of 7 layer-0 SAGE convs lose a full K=256 GEMM phase; type 2 becomes
//     a per-row 2-way select of precomputed normalized vectors.
//   - red.global.add.v4.f32 vector atomics in the scatter (4x fewer REDs).
//   - dropped bcast_init entirely.
// ---------------------------------------------------------------------------

#define DIM 256

static const int  NNODE[4]  = {100000, 50000, 200000, 150000}; // reaction, complex, protein, molecule
static const long XOFF[4]   = {0, 100000, 150000, 350000};     // row offsets in x buffers
static const int  ET_S[7]   = {2, 3, 1, 2, 3, 0, 0};
static const int  ET_D[7]   = {0, 0, 0, 1, 1, 2, 3};
static const long DEGOFF[7] = {0, 100000, 200000, 300000, 350000, 400000, 600000};
#define DEG_TOTAL 750000

// scratch (device globals: no cudaMalloc allowed)
__device__ float g_xA[128000000];   // 500k rows x 256
__device__ float g_xB[128000000];
__device__ float g_agg[51200000];   // max 200k rows x 256
__device__ float g_inv[DEG_TOTAL];
__device__ int   g_deg[DEG_TOTAL];
__device__ float g_r1[8 * 256];     // rank-1 vectors for layer 0
__device__ float g_two[2 * 256];    // type-2 precomputed normalized rows (w0, w1)

// ---- packed f32x2 helpers (FFMA2 path, sm_103a) ----------------------------
#define PACK2(out, lo, hi) \
    asm("mov.b64 %0, {%1, %2};" : "=l"(out) : "r"(__float_as_uint(lo)), "r"(__float_as_uint(hi)))
#define FMA2(acc, a, b) \
    asm("fma.rn.f32x2 %0, %1, %2, %0;" : "+l"(acc) : "l"(a), "l"(b))
#define UNPACK2(lo, hi, in) do { \
    unsigned _ul, _uh; \
    asm("mov.b64 {%0, %1}, %2;" : "=r"(_ul), "=r"(_uh) : "l"(in)); \
    lo = __uint_as_float(_ul); hi = __uint_as_float(_uh); } while (0)

__device__ __forceinline__ void red4(float* p, float4 v) {
    asm volatile("red.global.add.v4.f32 [%0], {%1,%2,%3,%4};"
                 :: "l"(p), "f"(v.x), "f"(v.y), "f"(v.z), "f"(v.w) : "memory");
}

__device__ __forceinline__ const float* resolve_x(const float* ext, int sel, long rowoff) {
    if (sel == 0) return g_xA + rowoff * DIM;
    if (sel == 1) return g_xB + rowoff * DIM;
    return ext;
}

// ---- small utility kernels --------------------------------------------------
__global__ void zero_deg_kernel() {
    int i = blockIdx.x * blockDim.x + threadIdx.x;
    if (i < DEG_TOTAL) g_deg[i] = 0;
}

__global__ void deg_kernel(const int* __restrict__ dstIdx, int e, long degOff) {
    int i = blockIdx.x * blockDim.x + threadIdx.x;
    if (i < e) atomicAdd(&g_deg[degOff + dstIdx[i]], 1);
}

__global__ void inv_kernel() {
    int i = blockIdx.x * blockDim.x + threadIdx.x;
    if (i < DEG_TOTAL) g_inv[i] = 1.0f / fmaxf((float)g_deg[i], 1.0f);
}

__global__ void zero_agg_kernel(long n4) {
    long i = (long)blockIdx.x * blockDim.x + threadIdx.x;
    if (i < n4) ((float4*)g_agg)[i] = make_float4(0.f, 0.f, 0.f, 0.f);
}

// y[j] = sum_k v[k] * W[k, j]   (v: 1x256, W: 256x256) — one block, 256 thr
__global__ void rank1_kernel(const float* __restrict__ v,
                             const float* __restrict__ W,
                             float* __restrict__ out) {
    int j = threadIdx.x;
    float acc = 0.f;
#pragma unroll 8
    for (int k = 0; k < 256; k++) acc += __ldg(&v[k]) * __ldg(&W[k * 256 + j]);
    out[j] = acc;
}

// type-2 layer-0: w1 = norm(vl + vr + b), w0 = norm(vr + b) — one block
__global__ void t2_combine_kernel(const float* __restrict__ vl,
                                  const float* __restrict__ vr,
                                  const float* __restrict__ b) {
    __shared__ float red[2][8];
    int j = threadIdx.x;
    float a0 = vr[j] + b[j];
    float a1 = a0 + vl[j];
    float s0 = a0 * a0, s1 = a1 * a1;
#pragma unroll
    for (int o = 16; o > 0; o >>= 1) {
        s0 += __shfl_xor_sync(0xffffffffu, s0, o);
        s1 += __shfl_xor_sync(0xffffffffu, s1, o);
    }
    if ((j & 31) == 0) { red[0][j >> 5] = s0; red[1][j >> 5] = s1; }
    __syncthreads();
    float t0 = 0.f, t1 = 0.f;
#pragma unroll
    for (int w = 0; w < 8; w++) { t0 += red[0][w]; t1 += red[1][w]; }
    g_two[j]       = a0 * (1.0f / fmaxf(sqrtf(t0), 1e-12f));
    g_two[256 + j] = a1 * (1.0f / fmaxf(sqrtf(t1), 1e-12f));
}

// accumulate per-row select of w0/w1 into Out (reaction rows of layer-0 out)
__global__ void t2_apply_kernel(float* __restrict__ Out, long degoff, int n) {
    long i = (long)blockIdx.x * blockDim.x + threadIdx.x;   // n*64 float4 lanes
    long r = i >> 6;
    int c = (int)(i & 63);
    if (r >= n) return;
    int gate = g_deg[degoff + r] > 0 ? 1 : 0;
    float4 w = ((const float4*)(g_two + gate * 256))[c];
    float4 u = ((float4*)(Out + r * DIM))[c];
    u.x += w.x; u.y += w.y; u.z += w.z; u.w += w.w;
    ((float4*)(Out + r * DIM))[c] = u;
}

// ---- scatter: warp per edge, v4 reduction atomics ---------------------------
__global__ void scatter_kernel(const float* __restrict__ ext, int sel, long rowoff,
                               const int* __restrict__ srcIdx,
                               const int* __restrict__ dstIdx,
                               int e, int relu) {
    int g = blockIdx.x * blockDim.x + threadIdx.x;
    int w = g >> 5;
    if (w >= e) return;
    int lane = g & 31;
    const float* X = resolve_x(ext, sel, rowoff);
    long s = srcIdx[w];
    long d = dstIdx[w];
    const float4* a = (const float4*)(X + s * DIM);
    float4 v0 = __ldg(&a[lane]);
    float4 v1 = __ldg(&a[lane + 32]);
    if (relu) {
        v0.x = fmaxf(v0.x, 0.f); v0.y = fmaxf(v0.y, 0.f);
        v0.z = fmaxf(v0.z, 0.f); v0.w = fmaxf(v0.w, 0.f);
        v1.x = fmaxf(v1.x, 0.f); v1.y = fmaxf(v1.y, 0.f);
        v1.z = fmaxf(v1.z, 0.f); v1.w = fmaxf(v1.w, 0.f);
    }
    float* o = g_agg + d * DIM;
    red4(o + lane * 4, v0);
    red4(o + 128 + lane * 4, v1);
}

// ---- fused SAGE GEMM --------------------------------------------------------
// out = [use_agg](agg*inv)@Bl + [use_x]relu?(A2)@Br + b + cvA + gate*cvG,
// row L2 norm, optional accumulate. BM=64, BN=256, BK=16, 256 threads.
__global__ __launch_bounds__(256, 2) void sage_gemm(
    const float* __restrict__ A2ext, int a2sel, long a2off,
    const float* __restrict__ Bl, const float* __restrict__ Br,
    const float* __restrict__ bias,
    const float* __restrict__ cvA, const float* __restrict__ cvG,
    int outsel, long outoff, long invoff,
    int n, int accum, int reluA2, int use_agg, int use_x) {
    __shared__ float As[16][64];
    __shared__ float Bs[16][256];

    const int tid = threadIdx.x;
    const long row0 = (long)blockIdx.x * 64;
    const int m = tid & 63, kq = tid >> 6;     // A load
    const int jb = tid & 63, kb = tid >> 6;    // B load
    const int tcol = tid & 31, tr = tid >> 5;  // compute

    const float* A2 = resolve_x(A2ext, a2sel, a2off);
    float* Out = ((outsel == 0) ? g_xA : g_xB) + outoff * DIM;

    unsigned long long acc[8][4];
#pragma unroll
    for (int i = 0; i < 8; i++)
#pragma unroll
        for (int p = 0; p < 4; p++) acc[i][p] = 0ULL;

    const long arow = row0 + m;
    const bool aval = arow < n;
    const float invm = (aval && use_agg) ? g_inv[invoff + arow] : 0.f;

#pragma unroll 1
    for (int ph = 0; ph < 2; ++ph) {
        if (ph == 0 && !use_agg) continue;
        if (ph == 1 && !use_x) continue;
        const float* Ag = ph ? A2 : g_agg;
        const float* Bg = ph ? Br : Bl;
#pragma unroll 1
        for (int k0 = 0; k0 < 256; k0 += 16) {
            float4 av = make_float4(0.f, 0.f, 0.f, 0.f);
            if (aval) av = *(const float4*)&Ag[arow * DIM + k0 + kq * 4];
            if (ph == 0) {
                av.x *= invm; av.y *= invm; av.z *= invm; av.w *= invm;
            } else if (reluA2) {
                av.x = fmaxf(av.x, 0.f); av.y = fmaxf(av.y, 0.f);
                av.z = fmaxf(av.z, 0.f); av.w = fmaxf(av.w, 0.f);
            }
            float4 bv[4];
#pragma unroll
            for (int r = 0; r < 4; r++)
                bv[r] = *(const float4*)&Bg[(long)(k0 + kb + r * 4) * DIM + jb * 4];
            __syncthreads();
            As[kq * 4 + 0][m] = av.x;
            As[kq * 4 + 1][m] = av.y;
            As[kq * 4 + 2][m] = av.z;
            As[kq * 4 + 3][m] = av.w;
#pragma unroll
            for (int r = 0; r < 4; r++)
                *(float4*)&Bs[kb + r * 4][jb * 4] = bv[r];
            __syncthreads();
#pragma unroll
            for (int k = 0; k < 16; k++) {
                ulonglong2 b01 = *(const ulonglong2*)&Bs[k][tcol * 4];
                ulonglong2 b23 = *(const ulonglong2*)&Bs[k][128 + tcol * 4];
                float4 a0 = *(const float4*)&As[k][tr * 8];
                float4 a1 = *(const float4*)&As[k][tr * 8 + 4];
                float aa[8] = {a0.x, a0.y, a0.z, a0.w, a1.x, a1.y, a1.z, a1.w};
#pragma unroll
                for (int i = 0; i < 8; i++) {
                    unsigned long long a2v;
                    PACK2(a2v, aa[i], aa[i]);
                    FMA2(acc[i][0], a2v, b01.x);
                    FMA2(acc[i][1], a2v, b01.y);
                    FMA2(acc[i][2], a2v, b23.x);
                    FMA2(acc[i][3], a2v, b23.y);
                }
            }
        }
    }

    // epilogue: +bias +cvA +gate*cvG, row L2 norm, accumulate store
    float bsv[8], cva[8], cvg[8];
    {
        float4 bb0 = *(const float4*)&bias[tcol * 4];
        float4 bb1 = *(const float4*)&bias[128 + tcol * 4];
        bsv[0]=bb0.x; bsv[1]=bb0.y; bsv[2]=bb0.z; bsv[3]=bb0.w;
        bsv[4]=bb1.x; bsv[5]=bb1.y; bsv[6]=bb1.z; bsv[7]=bb1.w;
    }
#pragma unroll
    for (int q = 0; q < 8; q++) { cva[q] = 0.f; cvg[q] = 0.f; }
    if (cvA) {
        float4 c0 = *(const float4*)&cvA[tcol * 4];
        float4 c1 = *(const float4*)&cvA[128 + tcol * 4];
        cva[0]=c0.x; cva[1]=c0.y; cva[2]=c0.z; cva[3]=c0.w;
        cva[4]=c1.x; cva[5]=c1.y; cva[6]=c1.z; cva[7]=c1.w;
    }
    if (cvG) {
        float4 c0 = *(const float4*)&cvG[tcol * 4];
        float4 c1 = *(const float4*)&cvG[128 + tcol * 4];
        cvg[0]=c0.x; cvg[1]=c0.y; cvg[2]=c0.z; cvg[3]=c0.w;
        cvg[4]=c1.x; cvg[5]=c1.y; cvg[6]=c1.z; cvg[7]=c1.w;
    }

#pragma unroll
    for (int i = 0; i < 8; i++) {
        long r = row0 + (long)tr * 8 + i;
        float gate = 0.f;
        if (cvG && r < n) gate = (g_deg[invoff + r] > 0) ? 1.f : 0.f;
        float v[8];
        UNPACK2(v[0], v[1], acc[i][0]);
        UNPACK2(v[2], v[3], acc[i][1]);
        UNPACK2(v[4], v[5], acc[i][2]);
        UNPACK2(v[6], v[7], acc[i][3]);
        float ss = 0.f;
#pragma unroll
        for (int q = 0; q < 8; q++) {
            v[q] += bsv[q] + cva[q] + gate * cvg[q];
            ss += v[q] * v[q];
        }
#pragma unroll
        for (int o = 16; o > 0; o >>= 1) ss += __shfl_xor_sync(0xffffffffu, ss, o);
        float sc = 1.0f / fmaxf(sqrtf(ss), 1e-12f);
        if (r < n) {
            float4 o0 = make_float4(v[0] * sc, v[1] * sc, v[2] * sc, v[3] * sc);
            float4 o1 = make_float4(v[4] * sc, v[5] * sc, v[6] * sc, v[7] * sc);
            float* op = Out + r * DIM;
            if (accum) {
                float4 u0 = *(float4*)&op[tcol * 4];
                float4 u1 = *(float4*)&op[128 + tcol * 4];
                o0.x += u0.x; o0.y += u0.y; o0.z += u0.z; o0.w += u0.w;
                o1.x += u1.x; o1.y += u1.y; o1.z += u1.z; o1.w += u1.w;
            }
            *(float4*)&op[tcol * 4] = o0;
            *(float4*)&op[128 + tcol * 4] = o1;
        }
    }
}

// ---- final head: relu(x_reaction) @ W_out[256x128] + b_out ------------------
__global__ __launch_bounds__(256, 2) void final_gemm(
    int asel, long aoff, const float* __restrict__ W,
    const float* __restrict__ bias, float* __restrict__ C, int n) {
    __shared__ float As[16][64];
    __shared__ float Bs[16][128];
    const int tid = threadIdx.x;
    const long row0 = (long)blockIdx.x * 64;
    const int m = tid & 63, kq = tid >> 6;
    const int jb = tid & 31, kb2 = tid >> 5;
    const int tcol = tid & 31, tr = tid >> 5;

    const float* A = resolve_x(nullptr, asel, aoff);

    unsigned long long acc[8][2];
#pragma unroll
    for (int i = 0; i < 8; i++) { acc[i][0] = 0ULL; acc[i][1] = 0ULL; }

    const long arow = row0 + m;
    const bool aval = arow < n;

#pragma unroll 1
    for (int k0 = 0; k0 < 256; k0 += 16) {
        float4 av = make_float4(0.f, 0.f, 0.f, 0.f);
        if (aval) av = *(const float4*)&A[arow * DIM + k0 + kq * 4];
        av.x = fmaxf(av.x, 0.f); av.y = fmaxf(av.y, 0.f);
        av.z = fmaxf(av.z, 0.f); av.w = fmaxf(av.w, 0.f);
        float4 bv0 = *(const float4*)&W[(long)(k0 + kb2) * 128 + jb * 4];
        float4 bv1 = *(const float4*)&W[(long)(k0 + kb2 + 8) * 128 + jb * 4];
        __syncthreads();
        As[kq * 4 + 0][m] = av.x;
        As[kq * 4 + 1][m] = av.y;
        As[kq * 4 + 2][m] = av.z;
        As[kq * 4 + 3][m] = av.w;
        *(float4*)&Bs[kb2][jb * 4] = bv0;
        *(float4*)&Bs[kb2 + 8][jb * 4] = bv1;
        __syncthreads();
#pragma unroll
        for (int k = 0; k < 16; k++) {
            ulonglong2 b01 = *(const ulonglong2*)&Bs[k][tcol * 4];
            float4 a0 = *(const float4*)&As[k][tr * 8];
            float4 a1 = *(const float4*)&As[k][tr * 8 + 4];
            float aa[8] = {a0.x, a0.y, a0.z, a0.w, a1.x, a1.y, a1.z, a1.w};
#pragma unroll
            for (int i = 0; i < 8; i++) {
                unsigned long long a2v;
                PACK2(a2v, aa[i], aa[i]);
                FMA2(acc[i][0], a2v, b01.x);
                FMA2(acc[i][1], a2v, b01.y);
            }
        }
    }

    float4 bb = *(const float4*)&bias[tcol * 4];
    float bsv[4] = {bb.x, bb.y, bb.z, bb.w};
#pragma unroll
    for (int i = 0; i < 8; i++) {
        float v[4];
        UNPACK2(v[0], v[1], acc[i][0]);
        UNPACK2(v[2], v[3], acc[i][1]);
        long r = row0 + (long)tr * 8 + i;
        if (r < n) {
            float4 o0 = make_float4(v[0] + bsv[0], v[1] + bsv[1],
                                    v[2] + bsv[2], v[3] + bsv[3]);
            *(float4*)&C[r * 128 + tcol * 4] = o0;
        }
    }
}

// ---------------------------------------------------------------------------
extern "C" void kernel_launch(void* const* d_in, const int* in_sizes, int n_in,
                              void* d_out, int out_size) {
    const float* remb = (const float*)d_in[4];
    const float* cemb = (const float*)d_in[5];
    const float* ptab = (const float*)d_in[6];
    const float* mtab = (const float*)d_in[7];
    const float* Wl   = (const float*)d_in[8];
    const float* Wr   = (const float*)d_in[9];
    const float* bvec = (const float*)d_in[10];
    const float* Wout = (const float*)d_in[11];
    const float* bout = (const float*)d_in[12];
    const int* edge[7];
    int ecnt[7];
    for (int t = 0; t < 7; t++) {
        edge[t] = (const int*)d_in[13 + t];
        ecnt[t] = in_sizes[13 + t] / 2;   // [2, E]
    }

    // degrees (constant across layers) -> inv = 1/max(deg,1)
    zero_deg_kernel<<<(DEG_TOTAL + 255) / 256, 256>>>();
    for (int t = 0; t < 7; t++)
        deg_kernel<<<(ecnt[t] + 255) / 256, 256>>>(edge[t] + ecnt[t], ecnt[t], DEGOFF[t]);
    inv_kernel<<<(DEG_TOTAL + 255) / 256, 256>>>();

    // layer-0 rank-1 vectors.
    // slots: 0=vr0 (r@Wr[0,0]) 1=vr1 2=vl2 (c@Wl[0,2]) 3=vr2 4=vr3 (c@Wr[0,3])
    //        5=vr4 6=vl5 (r@Wl[0,5]) 7=vl6 (r@Wl[0,6])
    float* r1 = nullptr;
    cudaGetSymbolAddress((void**)&r1, g_r1);
    rank1_kernel<<<1, 256>>>(remb, Wr + 0 * 65536L, r1 + 0 * 256);
    rank1_kernel<<<1, 256>>>(remb, Wr + 1 * 65536L, r1 + 1 * 256);
    rank1_kernel<<<1, 256>>>(cemb, Wl + 2 * 65536L, r1 + 2 * 256);
    rank1_kernel<<<1, 256>>>(remb, Wr + 2 * 65536L, r1 + 3 * 256);
    rank1_kernel<<<1, 256>>>(cemb, Wr + 3 * 65536L, r1 + 4 * 256);
    rank1_kernel<<<1, 256>>>(cemb, Wr + 4 * 65536L, r1 + 5 * 256);
    rank1_kernel<<<1, 256>>>(remb, Wl + 5 * 65536L, r1 + 6 * 256);
    rank1_kernel<<<1, 256>>>(remb, Wl + 6 * 65536L, r1 + 7 * 256);
    t2_combine_kernel<<<1, 256>>>(r1 + 2 * 256, r1 + 3 * 256, bvec + 2 * 256);

    float* xB = nullptr;
    cudaGetSymbolAddress((void**)&xB, g_xB);

    // ---------------- layer 0 (rank-1 shortcuts) ----------------
    {
        // types 0,1: mean@Wl (GEMM) + vr const, dst reaction -> xB
        const float* src_ext[2] = {ptab, mtab};
        for (int t = 0; t < 2; t++) {
            int nd = NNODE[0], e = ecnt[t];
            long n4 = (long)nd * 64;
            zero_agg_kernel<<<(int)((n4 + 255) / 256), 256>>>(n4);
            scatter_kernel<<<(e * 32 + 255) / 256, 256>>>(
                src_ext[t], 2, 0, edge[t], edge[t] + e, e, 0);
            sage_gemm<<<(nd + 63) / 64, 256>>>(
                nullptr, 2, 0,
                Wl + (long)t * 65536, nullptr, bvec + (long)t * 256,
                r1 + t * 256, nullptr,
                1, XOFF[0], DEGOFF[t], nd, t == 0 ? 0 : 1, 0, 1, 0);
        }
        // type 2: per-row two-vector select, accum into reaction
        t2_apply_kernel<<<(NNODE[0] * 64 + 255) / 256, 256>>>(
            xB + XOFF[0] * DIM, DEGOFF[2], NNODE[0]);
        // types 3,4: mean@Wl + vr const, dst complex -> xB
        for (int t = 3; t < 5; t++) {
            int nd = NNODE[1], e = ecnt[t];
            long n4 = (long)nd * 64;
            zero_agg_kernel<<<(int)((n4 + 255) / 256), 256>>>(n4);
            scatter_kernel<<<(e * 32 + 255) / 256, 256>>>(
                src_ext[t - 3], 2, 0, edge[t], edge[t] + e, e, 0);
            sage_gemm<<<(nd + 63) / 64, 256>>>(
                nullptr, 2, 0,
                Wl + (long)t * 65536, nullptr, bvec + (long)t * 256,
                r1 + (t + 1) * 256, nullptr,
                1, XOFF[1], DEGOFF[t], nd, t == 3 ? 0 : 1, 0, 1, 0);
        }
        // type 5: gate*vl + ptab@Wr, dst protein
        sage_gemm<<<(NNODE[2] + 63) / 64, 256>>>(
            ptab, 2, 0, nullptr, Wr + 5L * 65536, bvec + 5L * 256,
            nullptr, r1 + 6 * 256,
            1, XOFF[2], DEGOFF[5], NNODE[2], 0, 0, 0, 1);
        // type 6: gate*vl + mtab@Wr, dst molecule
        sage_gemm<<<(NNODE[3] + 63) / 64, 256>>>(
            mtab, 2, 0, nullptr, Wr + 6L * 65536, bvec + 6L * 256,
            nullptr, r1 + 7 * 256,
            1, XOFF[3], DEGOFF[6], NNODE[3], 0, 0, 0, 1);
    }

    // ---------------- layers 1, 2 (full path) ----------------
    for (int l = 1; l < 3; l++) {
        int insel  = (l == 1) ? 1 : 0;   // l1 reads xB, l2 reads xA
        int osel   = (l == 1) ? 0 : 1;   // l1 -> xA, l2 -> xB
        int ntypes = (l == 2) ? 3 : 7;   // last layer: only dst 'reaction'
        bool first[4] = {true, true, true, true};
        for (int t = 0; t < ntypes; t++) {
            int s = ET_S[t], d = ET_D[t];
            int nd = NNODE[d], e = ecnt[t];
            long n4 = (long)nd * 64;
            zero_agg_kernel<<<(int)((n4 + 255) / 256), 256>>>(n4);
            scatter_kernel<<<(e * 32 + 255) / 256, 256>>>(
                nullptr, insel, XOFF[s], edge[t], edge[t] + e, e, 1);
            sage_gemm<<<(nd + 63) / 64, 256>>>(
                nullptr, insel, XOFF[d],
                Wl + (long)(l * 7 + t) * 65536,
                Wr + (long)(l * 7 + t) * 65536,
                bvec + (long)(l * 7 + t) * 256,
                nullptr, nullptr,
                osel, XOFF[d], DEGOFF[t], nd, first[d] ? 0 : 1, 1, 1, 1);
            first[d] = false;
        }
    }

    // head: relu(x_reaction layer-2, in g_xB) @ W_out + b_out
    final_gemm<<<(NNODE[0] + 63) / 64, 256>>>(1, XOFF[0], Wout, bout,
                                              (float*)d_out, NNODE[0]);
}

// round 3
// speedup vs baseline: 2.2606x; 1.0040x over previous
#include <cuda_runtime.h>

// ---------------------------------------------------------------------------
// HeteroGNN (3-layer hetero SAGE) on GB300 — Round 2.
//   R2 changes vs R1:
//   - layer-0 rank-1 algebra: broadcast reaction/complex embeddings mean that
//     5 of 7 layer-0 SAGE convs lose a full K=256 GEMM phase; type 2 becomes
//     a per-row 2-way select of precomputed normalized vectors.
//   - red.global.add.v4.f32 vector atomics in the scatter (4x fewer REDs).
//   - dropped bcast_init entirely.
// ---------------------------------------------------------------------------

#define DIM 256

static const int  NNODE[4]  = {100000, 50000, 200000, 150000}; // reaction, complex, protein, molecule
static const long XOFF[4]   = {0, 100000, 150000, 350000};     // row offsets in x buffers
static const int  ET_S[7]   = {2, 3, 1, 2, 3, 0, 0};
static const int  ET_D[7]   = {0, 0, 0, 1, 1, 2, 3};
static const long DEGOFF[7] = {0, 100000, 200000, 300000, 350000, 400000, 600000};
#define DEG_TOTAL 750000

// scratch (device globals: no cudaMalloc allowed)
__device__ float g_xA[128000000];   // 500k rows x 256
__device__ float g_xB[128000000];
__device__ float g_agg[51200000];   // max 200k rows x 256
__device__ float g_inv[DEG_TOTAL];
__device__ int   g_deg[DEG_TOTAL];
__device__ float g_r1[8 * 256];     // rank-1 vectors for layer 0
__device__ float g_two[2 * 256];    // type-2 precomputed normalized rows (w0, w1)

// ---- packed f32x2 helpers (FFMA2 path, sm_103a) ----------------------------
#define PACK2(out, lo, hi) \
    asm("mov.b64 %0, {%1, %2};" : "=l"(out) : "r"(__float_as_uint(lo)), "r"(__float_as_uint(hi)))
#define FMA2(acc, a, b) \
    asm("fma.rn.f32x2 %0, %1, %2, %0;" : "+l"(acc) : "l"(a), "l"(b))
#define UNPACK2(lo, hi, in) do { \
    unsigned _ul, _uh; \
    asm("mov.b64 {%0, %1}, %2;" : "=r"(_ul), "=r"(_uh) : "l"(in)); \
    lo = __uint_as_float(_ul); hi = __uint_as_float(_uh); } while (0)

__device__ __forceinline__ void red4(float* p, float4 v) {
    asm volatile("red.global.add.v4.f32 [%0], {%1,%2,%3,%4};"
                 :: "l"(p), "f"(v.x), "f"(v.y), "f"(v.z), "f"(v.w) : "memory");
}

__device__ __forceinline__ const float* resolve_x(const float* ext, int sel, long rowoff) {
    if (sel == 0) return g_xA + rowoff * DIM;
    if (sel == 1) return g_xB + rowoff * DIM;
    return ext;
}

// ---- small utility kernels --------------------------------------------------
__global__ void zero_deg_kernel() {
    int i = blockIdx.x * blockDim.x + threadIdx.x;
    if (i < DEG_TOTAL) g_deg[i] = 0;
}

__global__ void deg_kernel(const int* __restrict__ dstIdx, int e, long degOff) {
    int i = blockIdx.x * blockDim.x + threadIdx.x;
    if (i < e) atomicAdd(&g_deg[degOff + dstIdx[i]], 1);
}

__global__ void inv_kernel() {
    int i = blockIdx.x * blockDim.x + threadIdx.x;
    if (i < DEG_TOTAL) g_inv[i] = 1.0f / fmaxf((float)g_deg[i], 1.0f);
}

__global__ void zero_agg_kernel(long n4) {
    long i = (long)blockIdx.x * blockDim.x + threadIdx.x;
    if (i < n4) ((float4*)g_agg)[i] = make_float4(0.f, 0.f, 0.f, 0.f);
}

// y[j] = sum_k v[k] * W[k, j]   (v: 1x256, W: 256x256) — one block, 256 thr
__global__ void rank1_kernel(const float* __restrict__ v,
                             const float* __restrict__ W,
                             float* __restrict__ out) {
    int j = threadIdx.x;
    float acc = 0.f;
#pragma unroll 8
    for (int k = 0; k < 256; k++) acc += __ldg(&v[k]) * __ldg(&W[k * 256 + j]);
    out[j] = acc;
}

// type-2 layer-0: w1 = norm(vl + vr + b), w0 = norm(vr + b) — one block
__global__ void t2_combine_kernel(const float* __restrict__ vl,
                                  const float* __restrict__ vr,
                                  const float* __restrict__ b) {
    __shared__ float red[2][8];
    int j = threadIdx.x;
    float a0 = vr[j] + b[j];
    float a1 = a0 + vl[j];
    float s0 = a0 * a0, s1 = a1 * a1;
#pragma unroll
    for (int o = 16; o > 0; o >>= 1) {
        s0 += __shfl_xor_sync(0xffffffffu, s0, o);
        s1 += __shfl_xor_sync(0xffffffffu, s1, o);
    }
    if ((j & 31) == 0) { red[0][j >> 5] = s0; red[1][j >> 5] = s1; }
    __syncthreads();
    float t0 = 0.f, t1 = 0.f;
#pragma unroll
    for (int w = 0; w < 8; w++) { t0 += red[0][w]; t1 += red[1][w]; }
    g_two[j]       = a0 * (1.0f / fmaxf(sqrtf(t0), 1e-12f));
    g_two[256 + j] = a1 * (1.0f / fmaxf(sqrtf(t1), 1e-12f));
}

// accumulate per-row select of w0/w1 into Out (reaction rows of layer-0 out)
__global__ void t2_apply_kernel(float* __restrict__ Out, long degoff, int n) {
    long i = (long)blockIdx.x * blockDim.x + threadIdx.x;   // n*64 float4 lanes
    long r = i >> 6;
    int c = (int)(i & 63);
    if (r >= n) return;
    int gate = g_deg[degoff + r] > 0 ? 1 : 0;
    float4 w = ((const float4*)(g_two + gate * 256))[c];
    float4 u = ((float4*)(Out + r * DIM))[c];
    u.x += w.x; u.y += w.y; u.z += w.z; u.w += w.w;
    ((float4*)(Out + r * DIM))[c] = u;
}

// ---- scatter: warp per edge, v4 reduction atomics ---------------------------
__global__ void scatter_kernel(const float* __restrict__ ext, int sel, long rowoff,
                               const int* __restrict__ srcIdx,
                               const int* __restrict__ dstIdx,
                               int e, int relu) {
    int g = blockIdx.x * blockDim.x + threadIdx.x;
    int w = g >> 5;
    if (w >= e) return;
    int lane = g & 31;
    const float* X = resolve_x(ext, sel, rowoff);
    long s = srcIdx[w];
    long d = dstIdx[w];
    const float4* a = (const float4*)(X + s * DIM);
    float4 v0 = __ldg(&a[lane]);
    float4 v1 = __ldg(&a[lane + 32]);
    if (relu) {
        v0.x = fmaxf(v0.x, 0.f); v0.y = fmaxf(v0.y, 0.f);
        v0.z = fmaxf(v0.z, 0.f); v0.w = fmaxf(v0.w, 0.f);
        v1.x = fmaxf(v1.x, 0.f); v1.y = fmaxf(v1.y, 0.f);
        v1.z = fmaxf(v1.z, 0.f); v1.w = fmaxf(v1.w, 0.f);
    }
    float* o = g_agg + d * DIM;
    red4(o + lane * 4, v0);
    red4(o + 128 + lane * 4, v1);
}

// ---- fused SAGE GEMM --------------------------------------------------------
// out = [use_agg](agg*inv)@Bl + [use_x]relu?(A2)@Br + b + cvA + gate*cvG,
// row L2 norm, optional accumulate. BM=64, BN=256, BK=16, 256 threads.
__global__ __launch_bounds__(256, 2) void sage_gemm(
    const float* __restrict__ A2ext, int a2sel, long a2off,
    const float* __restrict__ Bl, const float* __restrict__ Br,
    const float* __restrict__ bias,
    const float* __restrict__ cvA, const float* __restrict__ cvG,
    int outsel, long outoff, long invoff,
    int n, int accum, int reluA2, int use_agg, int use_x) {
    __shared__ float As[16][64];
    __shared__ float Bs[16][256];

    const int tid = threadIdx.x;
    const long row0 = (long)blockIdx.x * 64;
    const int m = tid & 63, kq = tid >> 6;     // A load
    const int jb = tid & 63, kb = tid >> 6;    // B load
    const int tcol = tid & 31, tr = tid >> 5;  // compute

    const float* A2 = resolve_x(A2ext, a2sel, a2off);
    float* Out = ((outsel == 0) ? g_xA : g_xB) + outoff * DIM;

    unsigned long long acc[8][4];
#pragma unroll
    for (int i = 0; i < 8; i++)
#pragma unroll
        for (int p = 0; p < 4; p++) acc[i][p] = 0ULL;

    const long arow = row0 + m;
    const bool aval = arow < n;
    const float invm = (aval && use_agg) ? g_inv[invoff + arow] : 0.f;

#pragma unroll 1
    for (int ph = 0; ph < 2; ++ph) {
        if (ph == 0 && !use_agg) continue;
        if (ph == 1 && !use_x) continue;
        const float* Ag = ph ? A2 : g_agg;
        const float* Bg = ph ? Br : Bl;
#pragma unroll 1
        for (int k0 = 0; k0 < 256; k0 += 16) {
            float4 av = make_float4(0.f, 0.f, 0.f, 0.f);
            if (aval) av = *(const float4*)&Ag[arow * DIM + k0 + kq * 4];
            if (ph == 0) {
                av.x *= invm; av.y *= invm; av.z *= invm; av.w *= invm;
            } else if (reluA2) {
                av.x = fmaxf(av.x, 0.f); av.y = fmaxf(av.y, 0.f);
                av.z = fmaxf(av.z, 0.f); av.w = fmaxf(av.w, 0.f);
            }
            float4 bv[4];
#pragma unroll
            for (int r = 0; r < 4; r++)
                bv[r] = *(const float4*)&Bg[(long)(k0 + kb + r * 4) * DIM + jb * 4];
            __syncthreads();
            As[kq * 4 + 0][m] = av.x;
            As[kq * 4 + 1][m] = av.y;
            As[kq * 4 + 2][m] = av.z;
            As[kq * 4 + 3][m] = av.w;
#pragma unroll
            for (int r = 0; r < 4; r++)
                *(float4*)&Bs[kb + r * 4][jb * 4] = bv[r];
            __syncthreads();
#pragma unroll
            for (int k = 0; k < 16; k++) {
                ulonglong2 b01 = *(const ulonglong2*)&Bs[k][tcol * 4];
                ulonglong2 b23 = *(const ulonglong2*)&Bs[k][128 + tcol * 4];
                float4 a0 = *(const float4*)&As[k][tr * 8];
                float4 a1 = *(const float4*)&As[k][tr * 8 + 4];
                float aa[8] = {a0.x, a0.y, a0.z, a0.w, a1.x, a1.y, a1.z, a1.w};
#pragma unroll
                for (int i = 0; i < 8; i++) {
                    unsigned long long a2v;
                    PACK2(a2v, aa[i], aa[i]);
                    FMA2(acc[i][0], a2v, b01.x);
                    FMA2(acc[i][1], a2v, b01.y);
                    FMA2(acc[i][2], a2v, b23.x);
                    FMA2(acc[i][3], a2v, b23.y);
                }
            }
        }
    }

    // epilogue: +bias +cvA +gate*cvG, row L2 norm, accumulate store
    float bsv[8], cva[8], cvg[8];
    {
        float4 bb0 = *(const float4*)&bias[tcol * 4];
        float4 bb1 = *(const float4*)&bias[128 + tcol * 4];
        bsv[0]=bb0.x; bsv[1]=bb0.y; bsv[2]=bb0.z; bsv[3]=bb0.w;
        bsv[4]=bb1.x; bsv[5]=bb1.y; bsv[6]=bb1.z; bsv[7]=bb1.w;
    }
#pragma unroll
    for (int q = 0; q < 8; q++) { cva[q] = 0.f; cvg[q] = 0.f; }
    if (cvA) {
        float4 c0 = *(const float4*)&cvA[tcol * 4];
        float4 c1 = *(const float4*)&cvA[128 + tcol * 4];
        cva[0]=c0.x; cva[1]=c0.y; cva[2]=c0.z; cva[3]=c0.w;
        cva[4]=c1.x; cva[5]=c1.y; cva[6]=c1.z; cva[7]=c1.w;
    }
    if (cvG) {
        float4 c0 = *(const float4*)&cvG[tcol * 4];
        float4 c1 = *(const float4*)&cvG[128 + tcol * 4];
        cvg[0]=c0.x; cvg[1]=c0.y; cvg[2]=c0.z; cvg[3]=c0.w;
        cvg[4]=c1.x; cvg[5]=c1.y; cvg[6]=c1.z; cvg[7]=c1.w;
    }

#pragma unroll
    for (int i = 0; i < 8; i++) {
        long r = row0 + (long)tr * 8 + i;
        float gate = 0.f;
        if (cvG && r < n) gate = (g_deg[invoff + r] > 0) ? 1.f : 0.f;
        float v[8];
        UNPACK2(v[0], v[1], acc[i][0]);
        UNPACK2(v[2], v[3], acc[i][1]);
        UNPACK2(v[4], v[5], acc[i][2]);
        UNPACK2(v[6], v[7], acc[i][3]);
        float ss = 0.f;
#pragma unroll
        for (int q = 0; q < 8; q++) {
            v[q] += bsv[q] + cva[q] + gate * cvg[q];
            ss += v[q] * v[q];
        }
#pragma unroll
        for (int o = 16; o > 0; o >>= 1) ss += __shfl_xor_sync(0xffffffffu, ss, o);
        float sc = 1.0f / fmaxf(sqrtf(ss), 1e-12f);
        if (r < n) {
            float4 o0 = make_float4(v[0] * sc, v[1] * sc, v[2] * sc, v[3] * sc);
            float4 o1 = make_float4(v[4] * sc, v[5] * sc, v[6] * sc, v[7] * sc);
            float* op = Out + r * DIM;
            if (accum) {
                float4 u0 = *(float4*)&op[tcol * 4];
                float4 u1 = *(float4*)&op[128 + tcol * 4];
                o0.x += u0.x; o0.y += u0.y; o0.z += u0.z; o0.w += u0.w;
                o1.x += u1.x; o1.y += u1.y; o1.z += u1.z; o1.w += u1.w;
            }
            *(float4*)&op[tcol * 4] = o0;
            *(float4*)&op[128 + tcol * 4] = o1;
        }
    }
}

// ---- final head: relu(x_reaction) @ W_out[256x128] + b_out ------------------
__global__ __launch_bounds__(256, 2) void final_gemm(
    int asel, long aoff, const float* __restrict__ W,
    const float* __restrict__ bias, float* __restrict__ C, int n) {
    __shared__ float As[16][64];
    __shared__ float Bs[16][128];
    const int tid = threadIdx.x;
    const long row0 = (long)blockIdx.x * 64;
    const int m = tid & 63, kq = tid >> 6;
    const int jb = tid & 31, kb2 = tid >> 5;
    const int tcol = tid & 31, tr = tid >> 5;

    const float* A = resolve_x(nullptr, asel, aoff);

    unsigned long long acc[8][2];
#pragma unroll
    for (int i = 0; i < 8; i++) { acc[i][0] = 0ULL; acc[i][1] = 0ULL; }

    const long arow = row0 + m;
    const bool aval = arow < n;

#pragma unroll 1
    for (int k0 = 0; k0 < 256; k0 += 16) {
        float4 av = make_float4(0.f, 0.f, 0.f, 0.f);
        if (aval) av = *(const float4*)&A[arow * DIM + k0 + kq * 4];
        av.x = fmaxf(av.x, 0.f); av.y = fmaxf(av.y, 0.f);
        av.z = fmaxf(av.z, 0.f); av.w = fmaxf(av.w, 0.f);
        float4 bv0 = *(const float4*)&W[(long)(k0 + kb2) * 128 + jb * 4];
        float4 bv1 = *(const float4*)&W[(long)(k0 + kb2 + 8) * 128 + jb * 4];
        __syncthreads();
        As[kq * 4 + 0][m] = av.x;
        As[kq * 4 + 1][m] = av.y;
        As[kq * 4 + 2][m] = av.z;
        As[kq * 4 + 3][m] = av.w;
        *(float4*)&Bs[kb2][jb * 4] = bv0;
        *(float4*)&Bs[kb2 + 8][jb * 4] = bv1;
        __syncthreads();
#pragma unroll
        for (int k = 0; k < 16; k++) {
            ulonglong2 b01 = *(const ulonglong2*)&Bs[k][tcol * 4];
            float4 a0 = *(const float4*)&As[k][tr * 8];
            float4 a1 = *(const float4*)&As[k][tr * 8 + 4];
            float aa[8] = {a0.x, a0.y, a0.z, a0.w, a1.x, a1.y, a1.z, a1.w};
#pragma unroll
            for (int i = 0; i < 8; i++) {
                unsigned long long a2v;
                PACK2(a2v, aa[i], aa[i]);
                FMA2(acc[i][0], a2v, b01.x);
                FMA2(acc[i][1], a2v, b01.y);
            }
        }
    }

    float4 bb = *(const float4*)&bias[tcol * 4];
    float bsv[4] = {bb.x, bb.y, bb.z, bb.w};
#pragma unroll
    for (int i = 0; i < 8; i++) {
        float v[4];
        UNPACK2(v[0], v[1], acc[i][0]);
        UNPACK2(v[2], v[3], acc[i][1]);
        long r = row0 + (long)tr * 8 + i;
        if (r < n) {
            float4 o0 = make_float4(v[0] + bsv[0], v[1] + bsv[1],
                                    v[2] + bsv[2], v[3] + bsv[3]);
            *(float4*)&C[r * 128 + tcol * 4] = o0;
        }
    }
}

// ---------------------------------------------------------------------------
extern "C" void kernel_launch(void* const* d_in, const int* in_sizes, int n_in,
                              void* d_out, int out_size) {
    const float* remb = (const float*)d_in[4];
    const float* cemb = (const float*)d_in[5];
    const float* ptab = (const float*)d_in[6];
    const float* mtab = (const float*)d_in[7];
    const float* Wl   = (const float*)d_in[8];
    const float* Wr   = (const float*)d_in[9];
    const float* bvec = (const float*)d_in[10];
    const float* Wout = (const float*)d_in[11];
    const float* bout = (const float*)d_in[12];
    const int* edge[7];
    int ecnt[7];
    for (int t = 0; t < 7; t++) {
        edge[t] = (const int*)d_in[13 + t];
        ecnt[t] = in_sizes[13 + t] / 2;   // [2, E]
    }

    // degrees (constant across layers) -> inv = 1/max(deg,1)
    zero_deg_kernel<<<(DEG_TOTAL + 255) / 256, 256>>>();
    for (int t = 0; t < 7; t++)
        deg_kernel<<<(ecnt[t] + 255) / 256, 256>>>(edge[t] + ecnt[t], ecnt[t], DEGOFF[t]);
    inv_kernel<<<(DEG_TOTAL + 255) / 256, 256>>>();

    // layer-0 rank-1 vectors.
    // slots: 0=vr0 (r@Wr[0,0]) 1=vr1 2=vl2 (c@Wl[0,2]) 3=vr2 4=vr3 (c@Wr[0,3])
    //        5=vr4 6=vl5 (r@Wl[0,5]) 7=vl6 (r@Wl[0,6])
    float* r1 = nullptr;
    cudaGetSymbolAddress((void**)&r1, g_r1);
    rank1_kernel<<<1, 256>>>(remb, Wr + 0 * 65536L, r1 + 0 * 256);
    rank1_kernel<<<1, 256>>>(remb, Wr + 1 * 65536L, r1 + 1 * 256);
    rank1_kernel<<<1, 256>>>(cemb, Wl + 2 * 65536L, r1 + 2 * 256);
    rank1_kernel<<<1, 256>>>(remb, Wr + 2 * 65536L, r1 + 3 * 256);
    rank1_kernel<<<1, 256>>>(cemb, Wr + 3 * 65536L, r1 + 4 * 256);
    rank1_kernel<<<1, 256>>>(cemb, Wr + 4 * 65536L, r1 + 5 * 256);
    rank1_kernel<<<1, 256>>>(remb, Wl + 5 * 65536L, r1 + 6 * 256);
    rank1_kernel<<<1, 256>>>(remb, Wl + 6 * 65536L, r1 + 7 * 256);
    t2_combine_kernel<<<1, 256>>>(r1 + 2 * 256, r1 + 3 * 256, bvec + 2 * 256);

    float* xB = nullptr;
    cudaGetSymbolAddress((void**)&xB, g_xB);

    // ---------------- layer 0 (rank-1 shortcuts) ----------------
    {
        // types 0,1: mean@Wl (GEMM) + vr const, dst reaction -> xB
        const float* src_ext[2] = {ptab, mtab};
        for (int t = 0; t < 2; t++) {
            int nd = NNODE[0], e = ecnt[t];
            long n4 = (long)nd * 64;
            zero_agg_kernel<<<(int)((n4 + 255) / 256), 256>>>(n4);
            scatter_kernel<<<(e * 32 + 255) / 256, 256>>>(
                src_ext[t], 2, 0, edge[t], edge[t] + e, e, 0);
            sage_gemm<<<(nd + 63) / 64, 256>>>(
                nullptr, 2, 0,
                Wl + (long)t * 65536, nullptr, bvec + (long)t * 256,
                r1 + t * 256, nullptr,
                1, XOFF[0], DEGOFF[t], nd, t == 0 ? 0 : 1, 0, 1, 0);
        }
        // type 2: per-row two-vector select, accum into reaction
        t2_apply_kernel<<<(NNODE[0] * 64 + 255) / 256, 256>>>(
            xB + XOFF[0] * DIM, DEGOFF[2], NNODE[0]);
        // types 3,4: mean@Wl + vr const, dst complex -> xB
        for (int t = 3; t < 5; t++) {
            int nd = NNODE[1], e = ecnt[t];
            long n4 = (long)nd * 64;
            zero_agg_kernel<<<(int)((n4 + 255) / 256), 256>>>(n4);
            scatter_kernel<<<(e * 32 + 255) / 256, 256>>>(
                src_ext[t - 3], 2, 0, edge[t], edge[t] + e, e, 0);
            sage_gemm<<<(nd + 63) / 64, 256>>>(
                nullptr, 2, 0,
                Wl + (long)t * 65536, nullptr, bvec + (long)t * 256,
                r1 + (t + 1) * 256, nullptr,
                1, XOFF[1], DEGOFF[t], nd, t == 3 ? 0 : 1, 0, 1, 0);
        }
        // type 5: gate*vl + ptab@Wr, dst protein
        sage_gemm<<<(NNODE[2] + 63) / 64, 256>>>(
            ptab, 2, 0, nullptr, Wr + 5L * 65536, bvec + 5L * 256,
            nullptr, r1 + 6 * 256,
            1, XOFF[2], DEGOFF[5], NNODE[2], 0, 0, 0, 1);
        // type 6: gate*vl + mtab@Wr, dst molecule
        sage_gemm<<<(NNODE[3] + 63) / 64, 256>>>(
            mtab, 2, 0, nullptr, Wr + 6L * 65536, bvec + 6L * 256,
            nullptr, r1 + 7 * 256,
            1, XOFF[3], DEGOFF[6], NNODE[3], 0, 0, 0, 1);
    }

    // ---------------- layers 1, 2 (full path) ----------------
    for (int l = 1; l < 3; l++) {
        int insel  = (l == 1) ? 1 : 0;   // l1 reads xB, l2 reads xA
        int osel   = (l == 1) ? 0 : 1;   // l1 -> xA, l2 -> xB
        int ntypes = (l == 2) ? 3 : 7;   // last layer: only dst 'reaction'
        bool first[4] = {true, true, true, true};
        for (int t = 0; t < ntypes; t++) {
            int s = ET_S[t], d = ET_D[t];
            int nd = NNODE[d], e = ecnt[t];
            long n4 = (long)nd * 64;
            zero_agg_kernel<<<(int)((n4 + 255) / 256), 256>>>(n4);
            scatter_kernel<<<(e * 32 + 255) / 256, 256>>>(
                nullptr, insel, XOFF[s], edge[t], edge[t] + e, e, 1);
            sage_gemm<<<(nd + 63) / 64, 256>>>(
                nullptr, insel, XOFF[d],
                Wl + (long)(l * 7 + t) * 65536,
                Wr + (long)(l * 7 + t) * 65536,
                bvec + (long)(l * 7 + t) * 256,
                nullptr, nullptr,
                osel, XOFF[d], DEGOFF[t], nd, first[d] ? 0 : 1, 1, 1, 1);
            first[d] = false;
        }
    }

    // head: relu(x_reaction layer-2, in g_xB) @ W_out + b_out
    final_gemm<<<(NNODE[0] + 63) / 64, 256>>>(1, XOFF[0], Wout, bout,
                                              (float*)d_out, NNODE[0]);
}

// round 6
// speedup vs baseline: 2.3752x; 1.0507x over previous
#include <cuda_runtime.h>
#include <cuda_bf16.h>
#include <cstdint>

// ---------------------------------------------------------------------------
// HeteroGNN (3-layer hetero SAGE) on GB300 — Round 6.
//   tcgen05 is unusable (harness PTX target is sm_103, not sm_103a).
//   SAGE GEMMs now use warp-level mma.sync bf16 (hi/lo split, 3 passes),
//   ldmatrix fragments, cp.async double-buffered K staging.
// ---------------------------------------------------------------------------

#define DIM 256

static const int  NNODE[4]  = {100000, 50000, 200000, 150000};
static const long XOFF[4]   = {0, 100000, 150000, 350000};
static const int  ET_S[7]   = {2, 3, 1, 2, 3, 0, 0};
static const int  ET_D[7]   = {0, 0, 0, 1, 1, 2, 3};
static const long DEGOFF[7] = {0, 100000, 200000, 300000, 350000, 400000, 600000};
#define DEG_TOTAL 750000

__device__ float g_xA[128000000];
__device__ float g_xB[128000000];
__device__ float g_agg[51200000];
__device__ float g_inv[DEG_TOTAL];
__device__ int   g_deg[DEG_TOTAL];
__device__ float g_r1[8 * 256];
__device__ float g_two[2 * 256];

__device__ __nv_bfloat16 g_Whi[21 * 256 * 512];  // [pair][N=256][K=512]
__device__ __nv_bfloat16 g_Wlo[21 * 256 * 512];
__device__ __nv_bfloat16 g_aggh[51200000];
__device__ __nv_bfloat16 g_aggl[51200000];
__device__ __nv_bfloat16 g_xh[128000000];
__device__ __nv_bfloat16 g_xl[128000000];

// ---- FFMA2 helpers (head GEMM) ---------------------------------------------
#define PACK2(out, lo, hi) \
    asm("mov.b64 %0, {%1, %2};" : "=l"(out) : "r"(__float_as_uint(lo)), "r"(__float_as_uint(hi)))
#define FMA2(acc, a, b) \
    asm("fma.rn.f32x2 %0, %1, %2, %0;" : "+l"(acc) : "l"(a), "l"(b))
#define UNPACK2(lo, hi, in) do { \
    unsigned _ul, _uh; \
    asm("mov.b64 {%0, %1}, %2;" : "=r"(_ul), "=r"(_uh) : "l"(in)); \
    lo = __uint_as_float(_ul); hi = __uint_as_float(_uh); } while (0)

__device__ __forceinline__ void red4(float* p, float4 v) {
    asm volatile("red.global.add.v4.f32 [%0], {%1,%2,%3,%4};"
                 :: "l"(p), "f"(v.x), "f"(v.y), "f"(v.z), "f"(v.w) : "memory");
}

// ---- mma.sync helpers (baseline PTX, works on plain sm_103 target) ----------
__device__ __forceinline__ uint32_t smem_u32(const void* p) {
    uint32_t a;
    asm("{ .reg .u64 t; cvta.to.shared.u64 t, %1; cvt.u32.u64 %0, t; }" : "=r"(a) : "l"(p));
    return a;
}
__device__ __forceinline__ void cp16(uint32_t dst, const void* src, int sz) {
    asm volatile("cp.async.cg.shared.global [%0], [%1], 16, %2;"
                 :: "r"(dst), "l"(src), "r"(sz) : "memory");
}
#define CP_COMMIT() asm volatile("cp.async.commit_group;" ::: "memory")
#define CP_WAIT(N)  asm volatile("cp.async.wait_group %0;" :: "n"(N) : "memory")

#define LDSM4(r0, r1, r2, r3, addr) \
    asm volatile("ldmatrix.sync.aligned.m8n8.x4.shared.b16 {%0,%1,%2,%3}, [%4];" \
                 : "=r"(r0), "=r"(r1), "=r"(r2), "=r"(r3) : "r"(addr))

#define MMA16816(c, a, b) \
    asm volatile("mma.sync.aligned.m16n8k16.row.col.f32.bf16.bf16.f32 " \
                 "{%0,%1,%2,%3}, {%4,%5,%6,%7}, {%8,%9}, {%0,%1,%2,%3};" \
                 : "+f"((c)[0]), "+f"((c)[1]), "+f"((c)[2]), "+f"((c)[3]) \
                 : "r"((a)[0]), "r"((a)[1]), "r"((a)[2]), "r"((a)[3]), \
                   "r"((b)[0]), "r"((b)[1]))

__device__ __forceinline__ const float* resolve_x(const float* ext, int sel, long rowoff) {
    if (sel == 0) return g_xA + rowoff * DIM;
    if (sel == 1) return g_xB + rowoff * DIM;
    return ext;
}
__device__ __forceinline__ void bsplit(float v, __nv_bfloat16& h, __nv_bfloat16& l) {
    h = __float2bfloat16(v);
    l = __float2bfloat16(v - __bfloat162float(h));
}

// ---- utility kernels ---------------------------------------------------------
__global__ void zero_deg_kernel() {
    int i = blockIdx.x * blockDim.x + threadIdx.x;
    if (i < DEG_TOTAL) g_deg[i] = 0;
}
__global__ void deg_kernel(const int* __restrict__ dstIdx, int e, long degOff) {
    int i = blockIdx.x * blockDim.x + threadIdx.x;
    if (i < e) atomicAdd(&g_deg[degOff + dstIdx[i]], 1);
}
__global__ void inv_kernel() {
    int i = blockIdx.x * blockDim.x + threadIdx.x;
    if (i < DEG_TOTAL) g_inv[i] = 1.0f / fmaxf((float)g_deg[i], 1.0f);
}
__global__ void zero_agg_kernel(long n4) {
    long i = (long)blockIdx.x * blockDim.x + threadIdx.x;
    if (i < n4) ((float4*)g_agg)[i] = make_float4(0.f, 0.f, 0.f, 0.f);
}
__global__ void rank1_kernel(const float* __restrict__ v, const float* __restrict__ W,
                             float* __restrict__ out) {
    int j = threadIdx.x;
    float acc = 0.f;
#pragma unroll 8
    for (int k = 0; k < 256; k++) acc += __ldg(&v[k]) * __ldg(&W[k * 256 + j]);
    out[j] = acc;
}
__global__ void t2_combine_kernel(const float* __restrict__ vl, const float* __restrict__ vr,
                                  const float* __restrict__ b) {
    __shared__ float red[2][8];
    int j = threadIdx.x;
    float a0 = vr[j] + b[j];
    float a1 = a0 + vl[j];
    float s0 = a0 * a0, s1 = a1 * a1;
#pragma unroll
    for (int o = 16; o > 0; o >>= 1) {
        s0 += __shfl_xor_sync(0xffffffffu, s0, o);
        s1 += __shfl_xor_sync(0xffffffffu, s1, o);
    }
    if ((j & 31) == 0) { red[0][j >> 5] = s0; red[1][j >> 5] = s1; }
    __syncthreads();
    float t0 = 0.f, t1 = 0.f;
#pragma unroll
    for (int w = 0; w < 8; w++) { t0 += red[0][w]; t1 += red[1][w]; }
    g_two[j]       = a0 * (1.0f / fmaxf(sqrtf(t0), 1e-12f));
    g_two[256 + j] = a1 * (1.0f / fmaxf(sqrtf(t1), 1e-12f));
}
__global__ void t2_apply_kernel(float* __restrict__ Out, long degoff, int n) {
    long i = (long)blockIdx.x * blockDim.x + threadIdx.x;
    long r = i >> 6;
    int c = (int)(i & 63);
    if (r >= n) return;
    int gate = g_deg[degoff + r] > 0 ? 1 : 0;
    float4 w = ((const float4*)(g_two + gate * 256))[c];
    float4 u = ((float4*)(Out + r * DIM))[c];
    u.x += w.x; u.y += w.y; u.z += w.z; u.w += w.w;
    ((float4*)(Out + r * DIM))[c] = u;
}

__global__ void scatter_kernel(const float* __restrict__ ext, int sel, long rowoff,
                               const int* __restrict__ srcIdx,
                               const int* __restrict__ dstIdx, int e, int relu) {
    int g = blockIdx.x * blockDim.x + threadIdx.x;
    int w = g >> 5;
    if (w >= e) return;
    int lane = g & 31;
    const float* X = resolve_x(ext, sel, rowoff);
    long s = srcIdx[w];
    long d = dstIdx[w];
    const float4* a = (const float4*)(X + s * DIM);
    float4 v0 = __ldg(&a[lane]);
    float4 v1 = __ldg(&a[lane + 32]);
    if (relu) {
        v0.x = fmaxf(v0.x, 0.f); v0.y = fmaxf(v0.y, 0.f);
        v0.z = fmaxf(v0.z, 0.f); v0.w = fmaxf(v0.w, 0.f);
        v1.x = fmaxf(v1.x, 0.f); v1.y = fmaxf(v1.y, 0.f);
        v1.z = fmaxf(v1.z, 0.f); v1.w = fmaxf(v1.w, 0.f);
    }
    float* o = g_agg + d * DIM;
    red4(o + lane * 4, v0);
    red4(o + 128 + lane * 4, v1);
}

// ---- conversion kernels -------------------------------------------------------
__global__ void conv_w_kernel(const float* __restrict__ Wl, const float* __restrict__ Wr) {
    long i = (long)blockIdx.x * blockDim.x + threadIdx.x;
    if (i >= 21L * 256 * 64) return;
    int p    = (int)(i / (256 * 64));
    int rem  = (int)(i % (256 * 64));
    int nrow = rem / 64;
    int k8   = (rem % 64) * 8;
    const float* base = ((k8 < 256) ? Wl : Wr) + (long)p * 65536;
    int kk = k8 & 255;
    __align__(16) __nv_bfloat16 h[8], l[8];
#pragma unroll
    for (int j = 0; j < 8; j++) {
        float v = __ldg(&base[(long)(kk + j) * 256 + nrow]);
        bsplit(v, h[j], l[j]);
    }
    long o = ((long)p * 256 + nrow) * 512 + k8;
    *(uint4*)(g_Whi + o) = *(const uint4*)h;
    *(uint4*)(g_Wlo + o) = *(const uint4*)l;
}

__global__ void conv_x_kernel(const float* __restrict__ src, long dstRow, long n8, int relu) {
    long i = (long)blockIdx.x * blockDim.x + threadIdx.x;
    if (i >= n8) return;
    float4 a = ((const float4*)src)[i * 2];
    float4 b = ((const float4*)src)[i * 2 + 1];
    if (relu) {
        a.x = fmaxf(a.x, 0.f); a.y = fmaxf(a.y, 0.f); a.z = fmaxf(a.z, 0.f); a.w = fmaxf(a.w, 0.f);
        b.x = fmaxf(b.x, 0.f); b.y = fmaxf(b.y, 0.f); b.z = fmaxf(b.z, 0.f); b.w = fmaxf(b.w, 0.f);
    }
    float v[8] = {a.x, a.y, a.z, a.w, b.x, b.y, b.z, b.w};
    __align__(16) __nv_bfloat16 h[8], l[8];
#pragma unroll
    for (int j = 0; j < 8; j++) bsplit(v[j], h[j], l[j]);
    *(uint4*)(g_xh + dstRow * 256 + i * 8) = *(const uint4*)h;
    *(uint4*)(g_xl + dstRow * 256 + i * 8) = *(const uint4*)l;
}

__global__ void agg_fin_kernel(long degoff, int n) {
    long i = (long)blockIdx.x * blockDim.x + threadIdx.x;
    if (i >= (long)n * 32) return;
    long row = i >> 5;
    float inv = g_inv[degoff + row];
    float4 a = ((const float4*)g_agg)[i * 2];
    float4 b = ((const float4*)g_agg)[i * 2 + 1];
    float v[8] = {a.x * inv, a.y * inv, a.z * inv, a.w * inv,
                  b.x * inv, b.y * inv, b.z * inv, b.w * inv};
    __align__(16) __nv_bfloat16 h[8], l[8];
#pragma unroll
    for (int j = 0; j < 8; j++) bsplit(v[j], h[j], l[j]);
    *(uint4*)(g_aggh + i * 8) = *(const uint4*)h;
    *(uint4*)(g_aggl + i * 8) = *(const uint4*)l;
}

// ---- mma.sync fused SAGE GEMM ------------------------------------------------
// C[64 x 256] = [agg_mean | relu(x)] (bf16 hi/lo) @ W (bf16 hi/lo), 3 passes,
// + bias + cvA + gate*cvG, row L2-norm, optional accumulate into Out.
// 8 warps: wm in {0,1} (rows), wn in {0..3} (cols); warp tile 32 x 64.
// SMEM: stages s in {0,1}: A[s][var][64][72] bf16, B[s][var][256][72] bf16.
#define A_STRIDE 144          // 72 bf16 per row
#define A_BLK    (64 * 144)   // 9216 B per (stage,var)
#define B_OFF    36864
#define B_BLK    (256 * 144)  // 36864 B per (stage,var)
#define CADD_OFF 184320
#define CVG_OFF  185344
#define RED_OFF  186368       // float[4][64]
#define SMEM_SZ  187392

__global__ __launch_bounds__(256, 1) void mma_sage(
    long xoff,
    const __nv_bfloat16* __restrict__ Wh, const __nv_bfloat16* __restrict__ Wlo_,
    const float* __restrict__ bias, const float* __restrict__ cvA,
    const float* __restrict__ cvG,
    float* __restrict__ Out, long degoff, int n, int accum, int nagg, int nx) {
    extern __shared__ char smem[];
    const int tid = threadIdx.x;
    const int lane = tid & 31, wid = tid >> 5;
    const int wm = wid >> 2, wn = wid & 3;
    const uint32_t sbase = smem_u32(smem);
    float* cadd   = (float*)(smem + CADD_OFF);
    float* cvgS   = (float*)(smem + CVG_OFF);
    float* rowred = (float*)(smem + RED_OFF);

    cadd[tid] = bias[tid] + (cvA ? cvA[tid] : 0.f);
    cvgS[tid] = cvG ? cvG[tid] : 0.f;

    const long row0 = (long)blockIdx.x * 64;
    const int nch = nagg + nx;

    float C[2][8][4];
#pragma unroll
    for (int mt = 0; mt < 2; mt++)
#pragma unroll
        for (int nt = 0; nt < 8; nt++)
#pragma unroll
            for (int q = 0; q < 4; q++) C[mt][nt][q] = 0.f;

    // producer mapping
    const int aslot = tid >> 1, avar = aslot >> 6, arow = aslot & 63;
    const int akh = (tid & 1) * 32;
    const long agrow = row0 + arow;
    const int asz = (agrow < n) ? 16 : 0;
    const long agc = (agrow < n) ? agrow : 0;

    auto issue = [&](int s, int c) {
        int kcol, wcol;
        const __nv_bfloat16 *Ah, *Al;
        if (c < nagg) { Ah = g_aggh; Al = g_aggl; kcol = c * 64; wcol = c * 64; }
        else {
            Ah = g_xh + xoff * 256; Al = g_xl + xoff * 256;
            kcol = (c - nagg) * 64; wcol = 256 + (c - nagg) * 64;
        }
        const __nv_bfloat16* asrc = (avar ? Al : Ah) + agc * 256 + kcol + akh;
        uint32_t adst = sbase + (uint32_t)(s * 2 + avar) * A_BLK + arow * A_STRIDE + akh * 2;
#pragma unroll
        for (int j = 0; j < 4; j++) cp16(adst + j * 16, asrc + j * 8, asz);
#pragma unroll
        for (int v = 0; v < 2; v++) {
            const __nv_bfloat16* b = (v ? Wlo_ : Wh) + (long)tid * 512 + wcol;
            uint32_t bdst = sbase + B_OFF + (uint32_t)(s * 2 + v) * B_BLK + tid * A_STRIDE;
#pragma unroll
            for (int j = 0; j < 8; j++) cp16(bdst + j * 16, b + j * 8, 16);
        }
        CP_COMMIT();
    };

    issue(0, 0);
    if (nch > 1) issue(1, 1);

    // ldmatrix lane addressing (constant per thread)
    const int a_r  = wm * 32 + (lane & 15);            // A row within block
    const int a_k8 = ((lane >> 4) & 1) * 8;            // A k sub-offset
    const int b_n  = ((lane >> 4) & 1) * 8 + (lane & 7);
    const int b_k8 = ((lane >> 3) & 1) * 8;

    for (int c = 0; c < nch; c++) {
        if (c + 1 < nch) { CP_WAIT(1); } else { CP_WAIT(0); }
        __syncthreads();
        const int s = c & 1;
        const uint32_t aBase = sbase + (uint32_t)(s * 2) * A_BLK;
        const uint32_t bBase = sbase + B_OFF + (uint32_t)(s * 2) * B_BLK;

#pragma unroll
        for (int k16 = 0; k16 < 4; k16++) {
            const int kb = k16 * 16;
            uint32_t ah[2][4], al[2][4], bh[8][2], bl[8][2];
#pragma unroll
            for (int mt = 0; mt < 2; mt++) {
                uint32_t ad = aBase + (a_r + mt * 16) * A_STRIDE + (kb + a_k8) * 2;
                LDSM4(ah[mt][0], ah[mt][1], ah[mt][2], ah[mt][3], ad);
                LDSM4(al[mt][0], al[mt][1], al[mt][2], al[mt][3], ad + A_BLK);
            }
#pragma unroll
            for (int np = 0; np < 4; np++) {
                uint32_t bd = bBase + (wn * 64 + np * 16 + b_n) * A_STRIDE + (kb + b_k8) * 2;
                LDSM4(bh[np*2][0], bh[np*2][1], bh[np*2+1][0], bh[np*2+1][1], bd);
                LDSM4(bl[np*2][0], bl[np*2][1], bl[np*2+1][0], bl[np*2+1][1], bd + B_BLK);
            }
#pragma unroll
            for (int mt = 0; mt < 2; mt++)
#pragma unroll
                for (int nt = 0; nt < 8; nt++) {
                    MMA16816(C[mt][nt], ah[mt], bh[nt]);
                    MMA16816(C[mt][nt], al[mt], bh[nt]);
                    MMA16816(C[mt][nt], ah[mt], bl[nt]);
                }
        }
        __syncthreads();
        if (c + 2 < nch) issue(s, c + 2);
    }

    // ---- epilogue ----
    // rows owned: for mt: r_lo = wm*32 + mt*16 + lane/4, r_hi = r_lo + 8
    float gate_lo[2], gate_hi[2];
#pragma unroll
    for (int mt = 0; mt < 2; mt++) {
        int rl = wm * 32 + mt * 16 + (lane >> 2);
        long grl = row0 + rl, grh = grl + 8;
        gate_lo[mt] = (cvG && grl < n) ? ((g_deg[degoff + grl] > 0) ? 1.f : 0.f) : 0.f;
        gate_hi[mt] = (cvG && grh < n) ? ((g_deg[degoff + grh] > 0) ? 1.f : 0.f) : 0.f;
    }
    float s_lo[2] = {0.f, 0.f}, s_hi[2] = {0.f, 0.f};
#pragma unroll
    for (int mt = 0; mt < 2; mt++)
#pragma unroll
        for (int nt = 0; nt < 8; nt++) {
            int col = wn * 64 + nt * 8 + (lane & 3) * 2;
            float c0 = cadd[col], c1 = cadd[col + 1];
            float g0 = cvgS[col], g1 = cvgS[col + 1];
            float v0 = C[mt][nt][0] + c0 + gate_lo[mt] * g0;
            float v1 = C[mt][nt][1] + c1 + gate_lo[mt] * g1;
            float v2 = C[mt][nt][2] + c0 + gate_hi[mt] * g0;
            float v3 = C[mt][nt][3] + c1 + gate_hi[mt] * g1;
            C[mt][nt][0] = v0; C[mt][nt][1] = v1; C[mt][nt][2] = v2; C[mt][nt][3] = v3;
            s_lo[mt] += v0 * v0 + v1 * v1;
            s_hi[mt] += v2 * v2 + v3 * v3;
        }
#pragma unroll
    for (int mt = 0; mt < 2; mt++) {
        s_lo[mt] += __shfl_xor_sync(0xffffffffu, s_lo[mt], 1);
        s_lo[mt] += __shfl_xor_sync(0xffffffffu, s_lo[mt], 2);
        s_hi[mt] += __shfl_xor_sync(0xffffffffu, s_hi[mt], 1);
        s_hi[mt] += __shfl_xor_sync(0xffffffffu, s_hi[mt], 2);
    }
    if ((lane & 3) == 0) {
#pragma unroll
        for (int mt = 0; mt < 2; mt++) {
            int rl = wm * 32 + mt * 16 + (lane >> 2);
            rowred[wn * 64 + rl]     = s_lo[mt];
            rowred[wn * 64 + rl + 8] = s_hi[mt];
        }
    }
    __syncthreads();
#pragma unroll
    for (int mt = 0; mt < 2; mt++) {
        int rl = wm * 32 + mt * 16 + (lane >> 2);
        int rh = rl + 8;
        float ssl = rowred[rl] + rowred[64 + rl] + rowred[128 + rl] + rowred[192 + rl];
        float ssh = rowred[rh] + rowred[64 + rh] + rowred[128 + rh] + rowred[192 + rh];
        float scl = 1.0f / fmaxf(sqrtf(ssl), 1e-12f);
        float sch = 1.0f / fmaxf(sqrtf(ssh), 1e-12f);
        long grl = row0 + rl, grh = row0 + rh;
#pragma unroll
        for (int nt = 0; nt < 8; nt++) {
            int col = wn * 64 + nt * 8 + (lane & 3) * 2;
            if (grl < n) {
                float2 o = make_float2(C[mt][nt][0] * scl, C[mt][nt][1] * scl);
                float* op = Out + grl * 256 + col;
                if (accum) { float2 u = *(const float2*)op; o.x += u.x; o.y += u.y; }
                *(float2*)op = o;
            }
            if (grh < n) {
                float2 o = make_float2(C[mt][nt][2] * sch, C[mt][nt][3] * sch);
                float* op = Out + grh * 256 + col;
                if (accum) { float2 u = *(const float2*)op; o.x += u.x; o.y += u.y; }
                *(float2*)op = o;
            }
        }
    }
}

// ---- final head: relu(x_reaction) @ W_out[256x128] + b_out -------------------
__global__ __launch_bounds__(256, 2) void final_gemm(
    int asel, long aoff, const float* __restrict__ W,
    const float* __restrict__ bias, float* __restrict__ C, int n) {
    __shared__ float As[16][64];
    __shared__ float Bs[16][128];
    const int tid = threadIdx.x;
    const long row0 = (long)blockIdx.x * 64;
    const int m = tid & 63, kq = tid >> 6;
    const int jb = tid & 31, kb2 = tid >> 5;
    const int tcol = tid & 31, tr = tid >> 5;

    const float* A = resolve_x(nullptr, asel, aoff);

    unsigned long long acc[8][2];
#pragma unroll
    for (int i = 0; i < 8; i++) { acc[i][0] = 0ULL; acc[i][1] = 0ULL; }

    const long arow = row0 + m;
    const bool aval = arow < n;

#pragma unroll 1
    for (int k0 = 0; k0 < 256; k0 += 16) {
        float4 av = make_float4(0.f, 0.f, 0.f, 0.f);
        if (aval) av = *(const float4*)&A[arow * DIM + k0 + kq * 4];
        av.x = fmaxf(av.x, 0.f); av.y = fmaxf(av.y, 0.f);
        av.z = fmaxf(av.z, 0.f); av.w = fmaxf(av.w, 0.f);
        float4 bv0 = *(const float4*)&W[(long)(k0 + kb2) * 128 + jb * 4];
        float4 bv1 = *(const float4*)&W[(long)(k0 + kb2 + 8) * 128 + jb * 4];
        __syncthreads();
        As[kq * 4 + 0][m] = av.x;
        As[kq * 4 + 1][m] = av.y;
        As[kq * 4 + 2][m] = av.z;
        As[kq * 4 + 3][m] = av.w;
        *(float4*)&Bs[kb2][jb * 4] = bv0;
        *(float4*)&Bs[kb2 + 8][jb * 4] = bv1;
        __syncthreads();
#pragma unroll
        for (int k = 0; k < 16; k++) {
            ulonglong2 b01 = *(const ulonglong2*)&Bs[k][tcol * 4];
            float4 a0 = *(const float4*)&As[k][tr * 8];
            float4 a1 = *(const float4*)&As[k][tr * 8 + 4];
            float aa[8] = {a0.x, a0.y, a0.z, a0.w, a1.x, a1.y, a1.z, a1.w};
#pragma unroll
            for (int i = 0; i < 8; i++) {
                unsigned long long a2v;
                PACK2(a2v, aa[i], aa[i]);
                FMA2(acc[i][0], a2v, b01.x);
                FMA2(acc[i][1], a2v, b01.y);
            }
        }
    }

    float4 bb = *(const float4*)&bias[tcol * 4];
    float bsv[4] = {bb.x, bb.y, bb.z, bb.w};
#pragma unroll
    for (int i = 0; i < 8; i++) {
        float v[4];
        UNPACK2(v[0], v[1], acc[i][0]);
        UNPACK2(v[2], v[3], acc[i][1]);
        long r = row0 + (long)tr * 8 + i;
        if (r < n) {
            float4 o0 = make_float4(v[0] + bsv[0], v[1] + bsv[1],
                                    v[2] + bsv[2], v[3] + bsv[3]);
            *(float4*)&C[r * 128 + tcol * 4] = o0;
        }
    }
}

// ---------------------------------------------------------------------------
extern "C" void kernel_launch(void* const* d_in, const int* in_sizes, int n_in,
                              void* d_out, int out_size) {
    const float* remb = (const float*)d_in[4];
    const float* cemb = (const float*)d_in[5];
    const float* ptab = (const float*)d_in[6];
    const float* mtab = (const float*)d_in[7];
    const float* Wl   = (const float*)d_in[8];
    const float* Wr   = (const float*)d_in[9];
    const float* bvec = (const float*)d_in[10];
    const float* Wout = (const float*)d_in[11];
    const float* bout = (const float*)d_in[12];
    const int* edge[7];
    int ecnt[7];
    for (int t = 0; t < 7; t++) {
        edge[t] = (const int*)d_in[13 + t];
        ecnt[t] = in_sizes[13 + t] / 2;
    }

    cudaFuncSetAttribute(mma_sage, cudaFuncAttributeMaxDynamicSharedMemorySize, SMEM_SZ);

    float *r1, *xA, *xB;
    __nv_bfloat16 *whi, *wlo;
    cudaGetSymbolAddress((void**)&r1, g_r1);
    cudaGetSymbolAddress((void**)&xA, g_xA);
    cudaGetSymbolAddress((void**)&xB, g_xB);
    cudaGetSymbolAddress((void**)&whi, g_Whi);
    cudaGetSymbolAddress((void**)&wlo, g_Wlo);

    // degrees -> inv
    zero_deg_kernel<<<(DEG_TOTAL + 255) / 256, 256>>>();
    for (int t = 0; t < 7; t++)
        deg_kernel<<<(ecnt[t] + 255) / 256, 256>>>(edge[t] + ecnt[t], ecnt[t], DEGOFF[t]);
    inv_kernel<<<(DEG_TOTAL + 255) / 256, 256>>>();

    // weight repack + layer-0 table conversion
    conv_w_kernel<<<(int)((21L * 256 * 64 + 255) / 256), 256>>>(Wl, Wr);
    conv_x_kernel<<<(int)((200000L * 32 + 255) / 256), 256>>>(ptab, XOFF[2], 200000L * 32, 0);
    conv_x_kernel<<<(int)((150000L * 32 + 255) / 256), 256>>>(mtab, XOFF[3], 150000L * 32, 0);

    // layer-0 rank-1 vectors
    rank1_kernel<<<1, 256>>>(remb, Wr + 0 * 65536L, r1 + 0 * 256);
    rank1_kernel<<<1, 256>>>(remb, Wr + 1 * 65536L, r1 + 1 * 256);
    rank1_kernel<<<1, 256>>>(cemb, Wl + 2 * 65536L, r1 + 2 * 256);
    rank1_kernel<<<1, 256>>>(remb, Wr + 2 * 65536L, r1 + 3 * 256);
    rank1_kernel<<<1, 256>>>(cemb, Wr + 3 * 65536L, r1 + 4 * 256);
    rank1_kernel<<<1, 256>>>(cemb, Wr + 4 * 65536L, r1 + 5 * 256);
    rank1_kernel<<<1, 256>>>(remb, Wl + 5 * 65536L, r1 + 6 * 256);
    rank1_kernel<<<1, 256>>>(remb, Wl + 6 * 65536L, r1 + 7 * 256);
    t2_combine_kernel<<<1, 256>>>(r1 + 2 * 256, r1 + 3 * 256, bvec + 2 * 256);

    const float* src_ext[2] = {ptab, mtab};

    // ---------------- layer 0 ----------------
    for (int t = 0; t < 2; t++) {     // dst reaction: agg GEMM + const
        int nd = NNODE[0], e = ecnt[t];
        zero_agg_kernel<<<(int)(((long)nd * 64 + 255) / 256), 256>>>((long)nd * 64);
        scatter_kernel<<<(e * 32 + 255) / 256, 256>>>(src_ext[t], 2, 0, edge[t], edge[t] + e, e, 0);
        agg_fin_kernel<<<(int)(((long)nd * 32 + 255) / 256), 256>>>(DEGOFF[t], nd);
        mma_sage<<<(nd + 63) / 64, 256, SMEM_SZ>>>(
            0, whi + (long)t * 131072, wlo + (long)t * 131072,
            bvec + (long)t * 256, r1 + t * 256, nullptr,
            xB + XOFF[0] * DIM, DEGOFF[t], nd, t == 0 ? 0 : 1, 4, 0);
    }
    t2_apply_kernel<<<(NNODE[0] * 64 + 255) / 256, 256>>>(xB + XOFF[0] * DIM, DEGOFF[2], NNODE[0]);
    for (int t = 3; t < 5; t++) {     // dst complex: agg GEMM + const
        int nd = NNODE[1], e = ecnt[t];
        zero_agg_kernel<<<(int)(((long)nd * 64 + 255) / 256), 256>>>((long)nd * 64);
        scatter_kernel<<<(e * 32 + 255) / 256, 256>>>(src_ext[t - 3], 2, 0, edge[t], edge[t] + e, e, 0);
        agg_fin_kernel<<<(int)(((long)nd * 32 + 255) / 256), 256>>>(DEGOFF[t], nd);
        mma_sage<<<(nd + 63) / 64, 256, SMEM_SZ>>>(
            0, whi + (long)t * 131072, wlo + (long)t * 131072,
            bvec + (long)t * 256, r1 + (t + 1) * 256, nullptr,
            xB + XOFF[1] * DIM, DEGOFF[t], nd, t == 3 ? 0 : 1, 4, 0);
    }
    // t5: gate*vl + ptab@Wr (x-phase only), dst protein
    mma_sage<<<(NNODE[2] + 63) / 64, 256, SMEM_SZ>>>(
        XOFF[2], whi + 5L * 131072, wlo + 5L * 131072,
        bvec + 5L * 256, nullptr, r1 + 6 * 256,
        xB + XOFF[2] * DIM, DEGOFF[5], NNODE[2], 0, 0, 4);
    // t6: gate*vl + mtab@Wr, dst molecule
    mma_sage<<<(NNODE[3] + 63) / 64, 256, SMEM_SZ>>>(
        XOFF[3], whi + 6L * 131072, wlo + 6L * 131072,
        bvec + 6L * 256, nullptr, r1 + 7 * 256,
        xB + XOFF[3] * DIM, DEGOFF[6], NNODE[3], 0, 0, 4);

    // ---------------- layer 1 (reads xB -> writes xA) ----------------
    conv_x_kernel<<<(int)((500000L * 32 + 255) / 256), 256>>>(xB, 0, 500000L * 32, 1);
    {
        bool first[4] = {true, true, true, true};
        for (int t = 0; t < 7; t++) {
            int s = ET_S[t], d = ET_D[t];
            int nd = NNODE[d], e = ecnt[t];
            zero_agg_kernel<<<(int)(((long)nd * 64 + 255) / 256), 256>>>((long)nd * 64);
            scatter_kernel<<<(e * 32 + 255) / 256, 256>>>(
                nullptr, 1, XOFF[s], edge[t], edge[t] + e, e, 1);
            agg_fin_kernel<<<(int)(((long)nd * 32 + 255) / 256), 256>>>(DEGOFF[t], nd);
            mma_sage<<<(nd + 63) / 64, 256, SMEM_SZ>>>(
                XOFF[d], whi + (long)(7 + t) * 131072, wlo + (long)(7 + t) * 131072,
                bvec + (long)(7 + t) * 256, nullptr, nullptr,
                xA + XOFF[d] * DIM, DEGOFF[t], nd, first[d] ? 0 : 1, 4, 4);
            first[d] = false;
        }
    }

    // ---------------- layer 2 (reads xA -> writes xB, dst reaction only) ------
    conv_x_kernel<<<(int)((100000L * 32 + 255) / 256), 256>>>(xA, 0, 100000L * 32, 1);
    for (int t = 0; t < 3; t++) {
        int s = ET_S[t];
        int nd = NNODE[0], e = ecnt[t];
        zero_agg_kernel<<<(int)(((long)nd * 64 + 255) / 256), 256>>>((long)nd * 64);
        scatter_kernel<<<(e * 32 + 255) / 256, 256>>>(
            nullptr, 0, XOFF[s], edge[t], edge[t] + e, e, 1);
        agg_fin_kernel<<<(int)(((long)nd * 32 + 255) / 256), 256>>>(DEGOFF[t], nd);
        mma_sage<<<(nd + 63) / 64, 256, SMEM_SZ>>>(
            XOFF[0], whi + (long)(14 + t) * 131072, wlo + (long)(14 + t) * 131072,
            bvec + (long)(14 + t) * 256, nullptr, nullptr,
            xB + XOFF[0] * DIM, DEGOFF[t], nd, t == 0 ? 0 : 1, 4, 4);
    }

    // head: relu(x_reaction, in xB) @ W_out + b_out
    final_gemm<<<(NNODE[0] + 63) / 64, 256>>>(1, XOFF[0], Wout, bout, (float*)d_out, NNODE[0]);
}

// round 7
// speedup vs baseline: 2.3819x; 1.0028x over previous
#include <cuda_runtime.h>
#include <cuda_bf16.h>
#include <cstdint>

// ---------------------------------------------------------------------------
// HeteroGNN (3-layer hetero SAGE) on GB300 — Round 6.
//   tcgen05 is unusable (harness PTX target is sm_103, not sm_103a).
//   SAGE GEMMs now use warp-level mma.sync bf16 (hi/lo split, 3 passes),
//   ldmatrix fragments, cp.async double-buffered K staging.
// ---------------------------------------------------------------------------

#define DIM 256

static const int  NNODE[4]  = {100000, 50000, 200000, 150000};
static const long XOFF[4]   = {0, 100000, 150000, 350000};
static const int  ET_S[7]   = {2, 3, 1, 2, 3, 0, 0};
static const int  ET_D[7]   = {0, 0, 0, 1, 1, 2, 3};
static const long DEGOFF[7] = {0, 100000, 200000, 300000, 350000, 400000, 600000};
#define DEG_TOTAL 750000

__device__ float g_xA[128000000];
__device__ float g_xB[128000000];
__device__ float g_agg[51200000];
__device__ float g_inv[DEG_TOTAL];
__device__ int   g_deg[DEG_TOTAL];
__device__ float g_r1[8 * 256];
__device__ float g_two[2 * 256];

__device__ __nv_bfloat16 g_Whi[21 * 256 * 512];  // [pair][N=256][K=512]
__device__ __nv_bfloat16 g_Wlo[21 * 256 * 512];
__device__ __nv_bfloat16 g_aggh[51200000];
__device__ __nv_bfloat16 g_aggl[51200000];
__device__ __nv_bfloat16 g_xh[128000000];
__device__ __nv_bfloat16 g_xl[128000000];

// ---- FFMA2 helpers (head GEMM) ---------------------------------------------
#define PACK2(out, lo, hi) \
    asm("mov.b64 %0, {%1, %2};" : "=l"(out) : "r"(__float_as_uint(lo)), "r"(__float_as_uint(hi)))
#define FMA2(acc, a, b) \
    asm("fma.rn.f32x2 %0, %1, %2, %0;" : "+l"(acc) : "l"(a), "l"(b))
#define UNPACK2(lo, hi, in) do { \
    unsigned _ul, _uh; \
    asm("mov.b64 {%0, %1}, %2;" : "=r"(_ul), "=r"(_uh) : "l"(in)); \
    lo = __uint_as_float(_ul); hi = __uint_as_float(_uh); } while (0)

__device__ __forceinline__ void red4(float* p, float4 v) {
    asm volatile("red.global.add.v4.f32 [%0], {%1,%2,%3,%4};"
                 :: "l"(p), "f"(v.x), "f"(v.y), "f"(v.z), "f"(v.w) : "memory");
}

// ---- mma.sync helpers (baseline PTX, works on plain sm_103 target) ----------
__device__ __forceinline__ uint32_t smem_u32(const void* p) {
    uint32_t a;
    asm("{ .reg .u64 t; cvta.to.shared.u64 t, %1; cvt.u32.u64 %0, t; }" : "=r"(a) : "l"(p));
    return a;
}
__device__ __forceinline__ void cp16(uint32_t dst, const void* src, int sz) {
    asm volatile("cp.async.cg.shared.global [%0], [%1], 16, %2;"
                 :: "r"(dst), "l"(src), "r"(sz) : "memory");
}
#define CP_COMMIT() asm volatile("cp.async.commit_group;" ::: "memory")
#define CP_WAIT(N)  asm volatile("cp.async.wait_group %0;" :: "n"(N) : "memory")

#define LDSM4(r0, r1, r2, r3, addr) \
    asm volatile("ldmatrix.sync.aligned.m8n8.x4.shared.b16 {%0,%1,%2,%3}, [%4];" \
                 : "=r"(r0), "=r"(r1), "=r"(r2), "=r"(r3) : "r"(addr))

#define MMA16816(c, a, b) \
    asm volatile("mma.sync.aligned.m16n8k16.row.col.f32.bf16.bf16.f32 " \
                 "{%0,%1,%2,%3}, {%4,%5,%6,%7}, {%8,%9}, {%0,%1,%2,%3};" \
                 : "+f"((c)[0]), "+f"((c)[1]), "+f"((c)[2]), "+f"((c)[3]) \
                 : "r"((a)[0]), "r"((a)[1]), "r"((a)[2]), "r"((a)[3]), \
                   "r"((b)[0]), "r"((b)[1]))

__device__ __forceinline__ const float* resolve_x(const float* ext, int sel, long rowoff) {
    if (sel == 0) return g_xA + rowoff * DIM;
    if (sel == 1) return g_xB + rowoff * DIM;
    return ext;
}
__device__ __forceinline__ void bsplit(float v, __nv_bfloat16& h, __nv_bfloat16& l) {
    h = __float2bfloat16(v);
    l = __float2bfloat16(v - __bfloat162float(h));
}

// ---- utility kernels ---------------------------------------------------------
__global__ void zero_deg_kernel() {
    int i = blockIdx.x * blockDim.x + threadIdx.x;
    if (i < DEG_TOTAL) g_deg[i] = 0;
}
__global__ void deg_kernel(const int* __restrict__ dstIdx, int e, long degOff) {
    int i = blockIdx.x * blockDim.x + threadIdx.x;
    if (i < e) atomicAdd(&g_deg[degOff + dstIdx[i]], 1);
}
__global__ void inv_kernel() {
    int i = blockIdx.x * blockDim.x + threadIdx.x;
    if (i < DEG_TOTAL) g_inv[i] = 1.0f / fmaxf((float)g_deg[i], 1.0f);
}
__global__ void zero_agg_kernel(long n4) {
    long i = (long)blockIdx.x * blockDim.x + threadIdx.x;
    if (i < n4) ((float4*)g_agg)[i] = make_float4(0.f, 0.f, 0.f, 0.f);
}
__global__ void rank1_kernel(const float* __restrict__ v, const float* __restrict__ W,
                             float* __restrict__ out) {
    int j = threadIdx.x;
    float acc = 0.f;
#pragma unroll 8
    for (int k = 0; k < 256; k++) acc += __ldg(&v[k]) * __ldg(&W[k * 256 + j]);
    out[j] = acc;
}
__global__ void t2_combine_kernel(const float* __restrict__ vl, const float* __restrict__ vr,
                                  const float* __restrict__ b) {
    __shared__ float red[2][8];
    int j = threadIdx.x;
    float a0 = vr[j] + b[j];
    float a1 = a0 + vl[j];
    float s0 = a0 * a0, s1 = a1 * a1;
#pragma unroll
    for (int o = 16; o > 0; o >>= 1) {
        s0 += __shfl_xor_sync(0xffffffffu, s0, o);
        s1 += __shfl_xor_sync(0xffffffffu, s1, o);
    }
    if ((j & 31) == 0) { red[0][j >> 5] = s0; red[1][j >> 5] = s1; }
    __syncthreads();
    float t0 = 0.f, t1 = 0.f;
#pragma unroll
    for (int w = 0; w < 8; w++) { t0 += red[0][w]; t1 += red[1][w]; }
    g_two[j]       = a0 * (1.0f / fmaxf(sqrtf(t0), 1e-12f));
    g_two[256 + j] = a1 * (1.0f / fmaxf(sqrtf(t1), 1e-12f));
}
__global__ void t2_apply_kernel(float* __restrict__ Out, long degoff, int n) {
    long i = (long)blockIdx.x * blockDim.x + threadIdx.x;
    long r = i >> 6;
    int c = (int)(i & 63);
    if (r >= n) return;
    int gate = g_deg[degoff + r] > 0 ? 1 : 0;
    float4 w = ((const float4*)(g_two + gate * 256))[c];
    float4 u = ((float4*)(Out + r * DIM))[c];
    u.x += w.x; u.y += w.y; u.z += w.z; u.w += w.w;
    ((float4*)(Out + r * DIM))[c] = u;
}

__global__ void scatter_kernel(const float* __restrict__ ext, int sel, long rowoff,
                               const int* __restrict__ srcIdx,
                               const int* __restrict__ dstIdx, int e, int relu) {
    int g = blockIdx.x * blockDim.x + threadIdx.x;
    int w = g >> 5;
    if (w >= e) return;
    int lane = g & 31;
    const float* X = resolve_x(ext, sel, rowoff);
    long s = srcIdx[w];
    long d = dstIdx[w];
    const float4* a = (const float4*)(X + s * DIM);
    float4 v0 = __ldg(&a[lane]);
    float4 v1 = __ldg(&a[lane + 32]);
    if (relu) {
        v0.x = fmaxf(v0.x, 0.f); v0.y = fmaxf(v0.y, 0.f);
        v0.z = fmaxf(v0.z, 0.f); v0.w = fmaxf(v0.w, 0.f);
        v1.x = fmaxf(v1.x, 0.f); v1.y = fmaxf(v1.y, 0.f);
        v1.z = fmaxf(v1.z, 0.f); v1.w = fmaxf(v1.w, 0.f);
    }
    float* o = g_agg + d * DIM;
    red4(o + lane * 4, v0);
    red4(o + 128 + lane * 4, v1);
}

// ---- conversion kernels -------------------------------------------------------
__global__ void conv_w_kernel(const float* __restrict__ Wl, const float* __restrict__ Wr) {
    long i = (long)blockIdx.x * blockDim.x + threadIdx.x;
    if (i >= 21L * 256 * 64) return;
    int p    = (int)(i / (256 * 64));
    int rem  = (int)(i % (256 * 64));
    int nrow = rem / 64;
    int k8   = (rem % 64) * 8;
    const float* base = ((k8 < 256) ? Wl : Wr) + (long)p * 65536;
    int kk = k8 & 255;
    __align__(16) __nv_bfloat16 h[8], l[8];
#pragma unroll
    for (int j = 0; j < 8; j++) {
        float v = __ldg(&base[(long)(kk + j) * 256 + nrow]);
        bsplit(v, h[j], l[j]);
    }
    long o = ((long)p * 256 + nrow) * 512 + k8;
    *(uint4*)(g_Whi + o) = *(const uint4*)h;
    *(uint4*)(g_Wlo + o) = *(const uint4*)l;
}

__global__ void conv_x_kernel(const float* __restrict__ src, long dstRow, long n8, int relu) {
    long i = (long)blockIdx.x * blockDim.x + threadIdx.x;
    if (i >= n8) return;
    float4 a = ((const float4*)src)[i * 2];
    float4 b = ((const float4*)src)[i * 2 + 1];
    if (relu) {
        a.x = fmaxf(a.x, 0.f); a.y = fmaxf(a.y, 0.f); a.z = fmaxf(a.z, 0.f); a.w = fmaxf(a.w, 0.f);
        b.x = fmaxf(b.x, 0.f); b.y = fmaxf(b.y, 0.f); b.z = fmaxf(b.z, 0.f); b.w = fmaxf(b.w, 0.f);
    }
    float v[8] = {a.x, a.y, a.z, a.w, b.x, b.y, b.z, b.w};
    __align__(16) __nv_bfloat16 h[8], l[8];
#pragma unroll
    for (int j = 0; j < 8; j++) bsplit(v[j], h[j], l[j]);
    *(uint4*)(g_xh + dstRow * 256 + i * 8) = *(const uint4*)h;
    *(uint4*)(g_xl + dstRow * 256 + i * 8) = *(const uint4*)l;
}

__global__ void agg_fin_kernel(long degoff, int n) {
    long i = (long)blockIdx.x * blockDim.x + threadIdx.x;
    if (i >= (long)n * 32) return;
    long row = i >> 5;
    float inv = g_inv[degoff + row];
    float4 a = ((const float4*)g_agg)[i * 2];
    float4 b = ((const float4*)g_agg)[i * 2 + 1];
    float v[8] = {a.x * inv, a.y * inv, a.z * inv, a.w * inv,
                  b.x * inv, b.y * inv, b.z * inv, b.w * inv};
    __align__(16) __nv_bfloat16 h[8], l[8];
#pragma unroll
    for (int j = 0; j < 8; j++) bsplit(v[j], h[j], l[j]);
    *(uint4*)(g_aggh + i * 8) = *(const uint4*)h;
    *(uint4*)(g_aggl + i * 8) = *(const uint4*)l;
}

// ---- mma.sync fused SAGE GEMM ------------------------------------------------
// C[64 x 256] = [agg_mean | relu(x)] (bf16 hi/lo) @ W (bf16 hi/lo), 3 passes,
// + bias + cvA + gate*cvG, row L2-norm, optional accumulate into Out.
// 8 warps: wm in {0,1} (rows), wn in {0..3} (cols); warp tile 32 x 64.
// SMEM: stages s in {0,1}: A[s][var][64][72] bf16, B[s][var][256][72] bf16.
#define A_STRIDE 144          // 72 bf16 per row
#define A_BLK    (64 * 144)   // 9216 B per (stage,var)
#define B_OFF    36864
#define B_BLK    (256 * 144)  // 36864 B per (stage,var)
#define CADD_OFF 184320
#define CVG_OFF  185344
#define RED_OFF  186368       // float[4][64]
#define SMEM_SZ  187392

__global__ __launch_bounds__(256, 1) void mma_sage(
    long xoff,
    const __nv_bfloat16* __restrict__ Wh, const __nv_bfloat16* __restrict__ Wlo_,
    const float* __restrict__ bias, const float* __restrict__ cvA,
    const float* __restrict__ cvG,
    float* __restrict__ Out, long degoff, int n, int accum, int nagg, int nx) {
    extern __shared__ char smem[];
    const int tid = threadIdx.x;
    const int lane = tid & 31, wid = tid >> 5;
    const int wm = wid >> 2, wn = wid & 3;
    const uint32_t sbase = smem_u32(smem);
    float* cadd   = (float*)(smem + CADD_OFF);
    float* cvgS   = (float*)(smem + CVG_OFF);
    float* rowred = (float*)(smem + RED_OFF);

    cadd[tid] = bias[tid] + (cvA ? cvA[tid] : 0.f);
    cvgS[tid] = cvG ? cvG[tid] : 0.f;

    const long row0 = (long)blockIdx.x * 64;
    const int nch = nagg + nx;

    float C[2][8][4];
#pragma unroll
    for (int mt = 0; mt < 2; mt++)
#pragma unroll
        for (int nt = 0; nt < 8; nt++)
#pragma unroll
            for (int q = 0; q < 4; q++) C[mt][nt][q] = 0.f;

    // producer mapping
    const int aslot = tid >> 1, avar = aslot >> 6, arow = aslot & 63;
    const int akh = (tid & 1) * 32;
    const long agrow = row0 + arow;
    const int asz = (agrow < n) ? 16 : 0;
    const long agc = (agrow < n) ? agrow : 0;

    auto issue = [&](int s, int c) {
        int kcol, wcol;
        const __nv_bfloat16 *Ah, *Al;
        if (c < nagg) { Ah = g_aggh; Al = g_aggl; kcol = c * 64; wcol = c * 64; }
        else {
            Ah = g_xh + xoff * 256; Al = g_xl + xoff * 256;
            kcol = (c - nagg) * 64; wcol = 256 + (c - nagg) * 64;
        }
        const __nv_bfloat16* asrc = (avar ? Al : Ah) + agc * 256 + kcol + akh;
        uint32_t adst = sbase + (uint32_t)(s * 2 + avar) * A_BLK + arow * A_STRIDE + akh * 2;
#pragma unroll
        for (int j = 0; j < 4; j++) cp16(adst + j * 16, asrc + j * 8, asz);
#pragma unroll
        for (int v = 0; v < 2; v++) {
            const __nv_bfloat16* b = (v ? Wlo_ : Wh) + (long)tid * 512 + wcol;
            uint32_t bdst = sbase + B_OFF + (uint32_t)(s * 2 + v) * B_BLK + tid * A_STRIDE;
#pragma unroll
            for (int j = 0; j < 8; j++) cp16(bdst + j * 16, b + j * 8, 16);
        }
        CP_COMMIT();
    };

    issue(0, 0);
    if (nch > 1) issue(1, 1);

    // ldmatrix lane addressing (constant per thread)
    const int a_r  = wm * 32 + (lane & 15);            // A row within block
    const int a_k8 = ((lane >> 4) & 1) * 8;            // A k sub-offset
    const int b_n  = ((lane >> 4) & 1) * 8 + (lane & 7);
    const int b_k8 = ((lane >> 3) & 1) * 8;

    for (int c = 0; c < nch; c++) {
        if (c + 1 < nch) { CP_WAIT(1); } else { CP_WAIT(0); }
        __syncthreads();
        const int s = c & 1;
        const uint32_t aBase = sbase + (uint32_t)(s * 2) * A_BLK;
        const uint32_t bBase = sbase + B_OFF + (uint32_t)(s * 2) * B_BLK;

#pragma unroll
        for (int k16 = 0; k16 < 4; k16++) {
            const int kb = k16 * 16;
            uint32_t ah[2][4], al[2][4], bh[8][2], bl[8][2];
#pragma unroll
            for (int mt = 0; mt < 2; mt++) {
                uint32_t ad = aBase + (a_r + mt * 16) * A_STRIDE + (kb + a_k8) * 2;
                LDSM4(ah[mt][0], ah[mt][1], ah[mt][2], ah[mt][3], ad);
                LDSM4(al[mt][0], al[mt][1], al[mt][2], al[mt][3], ad + A_BLK);
            }
#pragma unroll
            for (int np = 0; np < 4; np++) {
                uint32_t bd = bBase + (wn * 64 + np * 16 + b_n) * A_STRIDE + (kb + b_k8) * 2;
                LDSM4(bh[np*2][0], bh[np*2][1], bh[np*2+1][0], bh[np*2+1][1], bd);
                LDSM4(bl[np*2][0], bl[np*2][1], bl[np*2+1][0], bl[np*2+1][1], bd + B_BLK);
            }
#pragma unroll
            for (int mt = 0; mt < 2; mt++)
#pragma unroll
                for (int nt = 0; nt < 8; nt++) {
                    MMA16816(C[mt][nt], ah[mt], bh[nt]);
                    MMA16816(C[mt][nt], al[mt], bh[nt]);
                    MMA16816(C[mt][nt], ah[mt], bl[nt]);
                }
        }
        __syncthreads();
        if (c + 2 < nch) issue(s, c + 2);
    }

    // ---- epilogue ----
    // rows owned: for mt: r_lo = wm*32 + mt*16 + lane/4, r_hi = r_lo + 8
    float gate_lo[2], gate_hi[2];
#pragma unroll
    for (int mt = 0; mt < 2; mt++) {
        int rl = wm * 32 + mt * 16 + (lane >> 2);
        long grl = row0 + rl, grh = grl + 8;
        gate_lo[mt] = (cvG && grl < n) ? ((g_deg[degoff + grl] > 0) ? 1.f : 0.f) : 0.f;
        gate_hi[mt] = (cvG && grh < n) ? ((g_deg[degoff + grh] > 0) ? 1.f : 0.f) : 0.f;
    }
    float s_lo[2] = {0.f, 0.f}, s_hi[2] = {0.f, 0.f};
#pragma unroll
    for (int mt = 0; mt < 2; mt++)
#pragma unroll
        for (int nt = 0; nt < 8; nt++) {
            int col = wn * 64 + nt * 8 + (lane & 3) * 2;
            float c0 = cadd[col], c1 = cadd[col + 1];
            float g0 = cvgS[col], g1 = cvgS[col + 1];
            float v0 = C[mt][nt][0] + c0 + gate_lo[mt] * g0;
            float v1 = C[mt][nt][1] + c1 + gate_lo[mt] * g1;
            float v2 = C[mt][nt][2] + c0 + gate_hi[mt] * g0;
            float v3 = C[mt][nt][3] + c1 + gate_hi[mt] * g1;
            C[mt][nt][0] = v0; C[mt][nt][1] = v1; C[mt][nt][2] = v2; C[mt][nt][3] = v3;
            s_lo[mt] += v0 * v0 + v1 * v1;
            s_hi[mt] += v2 * v2 + v3 * v3;
        }
#pragma unroll
    for (int mt = 0; mt < 2; mt++) {
        s_lo[mt] += __shfl_xor_sync(0xffffffffu, s_lo[mt], 1);
        s_lo[mt] += __shfl_xor_sync(0xffffffffu, s_lo[mt], 2);
        s_hi[mt] += __shfl_xor_sync(0xffffffffu, s_hi[mt], 1);
        s_hi[mt] += __shfl_xor_sync(0xffffffffu, s_hi[mt], 2);
    }
    if ((lane & 3) == 0) {
#pragma unroll
        for (int mt = 0; mt < 2; mt++) {
            int rl = wm * 32 + mt * 16 + (lane >> 2);
            rowred[wn * 64 + rl]     = s_lo[mt];
            rowred[wn * 64 + rl + 8] = s_hi[mt];
        }
    }
    __syncthreads();
#pragma unroll
    for (int mt = 0; mt < 2; mt++) {
        int rl = wm * 32 + mt * 16 + (lane >> 2);
        int rh = rl + 8;
        float ssl = rowred[rl] + rowred[64 + rl] + rowred[128 + rl] + rowred[192 + rl];
        float ssh = rowred[rh] + rowred[64 + rh] + rowred[128 + rh] + rowred[192 + rh];
        float scl = 1.0f / fmaxf(sqrtf(ssl), 1e-12f);
        float sch = 1.0f / fmaxf(sqrtf(ssh), 1e-12f);
        long grl = row0 + rl, grh = row0 + rh;
#pragma unroll
        for (int nt = 0; nt < 8; nt++) {
            int col = wn * 64 + nt * 8 + (lane & 3) * 2;
            if (grl < n) {
                float2 o = make_float2(C[mt][nt][0] * scl, C[mt][nt][1] * scl);
                float* op = Out + grl * 256 + col;
                if (accum) { float2 u = *(const float2*)op; o.x += u.x; o.y += u.y; }
                *(float2*)op = o;
            }
            if (grh < n) {
                float2 o = make_float2(C[mt][nt][2] * sch, C[mt][nt][3] * sch);
                float* op = Out + grh * 256 + col;
                if (accum) { float2 u = *(const float2*)op; o.x += u.x; o.y += u.y; }
                *(float2*)op = o;
            }
        }
    }
}

// ---- final head: relu(x_reaction) @ W_out[256x128] + b_out -------------------
__global__ __launch_bounds__(256, 2) void final_gemm(
    int asel, long aoff, const float* __restrict__ W,
    const float* __restrict__ bias, float* __restrict__ C, int n) {
    __shared__ float As[16][64];
    __shared__ float Bs[16][128];
    const int tid = threadIdx.x;
    const long row0 = (long)blockIdx.x * 64;
    const int m = tid & 63, kq = tid >> 6;
    const int jb = tid & 31, kb2 = tid >> 5;
    const int tcol = tid & 31, tr = tid >> 5;

    const float* A = resolve_x(nullptr, asel, aoff);

    unsigned long long acc[8][2];
#pragma unroll
    for (int i = 0; i < 8; i++) { acc[i][0] = 0ULL; acc[i][1] = 0ULL; }

    const long arow = row0 + m;
    const bool aval = arow < n;

#pragma unroll 1
    for (int k0 = 0; k0 < 256; k0 += 16) {
        float4 av = make_float4(0.f, 0.f, 0.f, 0.f);
        if (aval) av = *(const float4*)&A[arow * DIM + k0 + kq * 4];
        av.x = fmaxf(av.x, 0.f); av.y = fmaxf(av.y, 0.f);
        av.z = fmaxf(av.z, 0.f); av.w = fmaxf(av.w, 0.f);
        float4 bv0 = *(const float4*)&W[(long)(k0 + kb2) * 128 + jb * 4];
        float4 bv1 = *(const float4*)&W[(long)(k0 + kb2 + 8) * 128 + jb * 4];
        __syncthreads();
        As[kq * 4 + 0][m] = av.x;
        As[kq * 4 + 1][m] = av.y;
        As[kq * 4 + 2][m] = av.z;
        As[kq * 4 + 3][m] = av.w;
        *(float4*)&Bs[kb2][jb * 4] = bv0;
        *(float4*)&Bs[kb2 + 8][jb * 4] = bv1;
        __syncthreads();
#pragma unroll
        for (int k = 0; k < 16; k++) {
            ulonglong2 b01 = *(const ulonglong2*)&Bs[k][tcol * 4];
            float4 a0 = *(const float4*)&As[k][tr * 8];
            float4 a1 = *(const float4*)&As[k][tr * 8 + 4];
            float aa[8] = {a0.x, a0.y, a0.z, a0.w, a1.x, a1.y, a1.z, a1.w};
#pragma unroll
            for (int i = 0; i < 8; i++) {
                unsigned long long a2v;
                PACK2(a2v, aa[i], aa[i]);
                FMA2(acc[i][0], a2v, b01.x);
                FMA2(acc[i][1], a2v, b01.y);
            }
        }
    }

    float4 bb = *(const float4*)&bias[tcol * 4];
    float bsv[4] = {bb.x, bb.y, bb.z, bb.w};
#pragma unroll
    for (int i = 0; i < 8; i++) {
        float v[4];
        UNPACK2(v[0], v[1], acc[i][0]);
        UNPACK2(v[2], v[3], acc[i][1]);
        long r = row0 + (long)tr * 8 + i;
        if (r < n) {
            float4 o0 = make_float4(v[0] + bsv[0], v[1] + bsv[1],
                                    v[2] + bsv[2], v[3] + bsv[3]);
            *(float4*)&C[r * 128 + tcol * 4] = o0;
        }
    }
}

// ---------------------------------------------------------------------------
extern "C" void kernel_launch(void* const* d_in, const int* in_sizes, int n_in,
                              void* d_out, int out_size) {
    const float* remb = (const float*)d_in[4];
    const float* cemb = (const float*)d_in[5];
    const float* ptab = (const float*)d_in[6];
    const float* mtab = (const float*)d_in[7];
    const float* Wl   = (const float*)d_in[8];
    const float* Wr   = (const float*)d_in[9];
    const float* bvec = (const float*)d_in[10];
    const float* Wout = (const float*)d_in[11];
    const float* bout = (const float*)d_in[12];
    const int* edge[7];
    int ecnt[7];
    for (int t = 0; t < 7; t++) {
        edge[t] = (const int*)d_in[13 + t];
        ecnt[t] = in_sizes[13 + t] / 2;
    }

    cudaFuncSetAttribute(mma_sage, cudaFuncAttributeMaxDynamicSharedMemorySize, SMEM_SZ);

    float *r1, *xA, *xB;
    __nv_bfloat16 *whi, *wlo;
    cudaGetSymbolAddress((void**)&r1, g_r1);
    cudaGetSymbolAddress((void**)&xA, g_xA);
    cudaGetSymbolAddress((void**)&xB, g_xB);
    cudaGetSymbolAddress((void**)&whi, g_Whi);
    cudaGetSymbolAddress((void**)&wlo, g_Wlo);

    // degrees -> inv
    zero_deg_kernel<<<(DEG_TOTAL + 255) / 256, 256>>>();
    for (int t = 0; t < 7; t++)
        deg_kernel<<<(ecnt[t] + 255) / 256, 256>>>(edge[t] + ecnt[t], ecnt[t], DEGOFF[t]);
    inv_kernel<<<(DEG_TOTAL + 255) / 256, 256>>>();

    // weight repack + layer-0 table conversion
    conv_w_kernel<<<(int)((21L * 256 * 64 + 255) / 256), 256>>>(Wl, Wr);
    conv_x_kernel<<<(int)((200000L * 32 + 255) / 256), 256>>>(ptab, XOFF[2], 200000L * 32, 0);
    conv_x_kernel<<<(int)((150000L * 32 + 255) / 256), 256>>>(mtab, XOFF[3], 150000L * 32, 0);

    // layer-0 rank-1 vectors
    rank1_kernel<<<1, 256>>>(remb, Wr + 0 * 65536L, r1 + 0 * 256);
    rank1_kernel<<<1, 256>>>(remb, Wr + 1 * 65536L, r1 + 1 * 256);
    rank1_kernel<<<1, 256>>>(cemb, Wl + 2 * 65536L, r1 + 2 * 256);
    rank1_kernel<<<1, 256>>>(remb, Wr + 2 * 65536L, r1 + 3 * 256);
    rank1_kernel<<<1, 256>>>(cemb, Wr + 3 * 65536L, r1 + 4 * 256);
    rank1_kernel<<<1, 256>>>(cemb, Wr + 4 * 65536L, r1 + 5 * 256);
    rank1_kernel<<<1, 256>>>(remb, Wl + 5 * 65536L, r1 + 6 * 256);
    rank1_kernel<<<1, 256>>>(remb, Wl + 6 * 65536L, r1 + 7 * 256);
    t2_combine_kernel<<<1, 256>>>(r1 + 2 * 256, r1 + 3 * 256, bvec + 2 * 256);

    const float* src_ext[2] = {ptab, mtab};

    // ---------------- layer 0 ----------------
    for (int t = 0; t < 2; t++) {     // dst reaction: agg GEMM + const
        int nd = NNODE[0], e = ecnt[t];
        zero_agg_kernel<<<(int)(((long)nd * 64 + 255) / 256), 256>>>((long)nd * 64);
        scatter_kernel<<<(e * 32 + 255) / 256, 256>>>(src_ext[t], 2, 0, edge[t], edge[t] + e, e, 0);
        agg_fin_kernel<<<(int)(((long)nd * 32 + 255) / 256), 256>>>(DEGOFF[t], nd);
        mma_sage<<<(nd + 63) / 64, 256, SMEM_SZ>>>(
            0, whi + (long)t * 131072, wlo + (long)t * 131072,
            bvec + (long)t * 256, r1 + t * 256, nullptr,
            xB + XOFF[0] * DIM, DEGOFF[t], nd, t == 0 ? 0 : 1, 4, 0);
    }
    t2_apply_kernel<<<(NNODE[0] * 64 + 255) / 256, 256>>>(xB + XOFF[0] * DIM, DEGOFF[2], NNODE[0]);
    for (int t = 3; t < 5; t++) {     // dst complex: agg GEMM + const
        int nd = NNODE[1], e = ecnt[t];
        zero_agg_kernel<<<(int)(((long)nd * 64 + 255) / 256), 256>>>((long)nd * 64);
        scatter_kernel<<<(e * 32 + 255) / 256, 256>>>(src_ext[t - 3], 2, 0, edge[t], edge[t] + e, e, 0);
        agg_fin_kernel<<<(int)(((long)nd * 32 + 255) / 256), 256>>>(DEGOFF[t], nd);
        mma_sage<<<(nd + 63) / 64, 256, SMEM_SZ>>>(
            0, whi + (long)t * 131072, wlo + (long)t * 131072,
            bvec + (long)t * 256, r1 + (t + 1) * 256, nullptr,
            xB + XOFF[1] * DIM, DEGOFF[t], nd, t == 3 ? 0 : 1, 4, 0);
    }
    // t5: gate*vl + ptab@Wr (x-phase only), dst protein
    mma_sage<<<(NNODE[2] + 63) / 64, 256, SMEM_SZ>>>(
        XOFF[2], whi + 5L * 131072, wlo + 5L * 131072,
        bvec + 5L * 256, nullptr, r1 + 6 * 256,
        xB + XOFF[2] * DIM, DEGOFF[5], NNODE[2], 0, 0, 4);
    // t6: gate*vl + mtab@Wr, dst molecule
    mma_sage<<<(NNODE[3] + 63) / 64, 256, SMEM_SZ>>>(
        XOFF[3], whi + 6L * 131072, wlo + 6L * 131072,
        bvec + 6L * 256, nullptr, r1 + 7 * 256,
        xB + XOFF[3] * DIM, DEGOFF[6], NNODE[3], 0, 0, 4);

    // ---------------- layer 1 (reads xB -> writes xA) ----------------
    conv_x_kernel<<<(int)((500000L * 32 + 255) / 256), 256>>>(xB, 0, 500000L * 32, 1);
    {
        bool first[4] = {true, true, true, true};
        for (int t = 0; t < 7; t++) {
            int s = ET_S[t], d = ET_D[t];
            int nd = NNODE[d], e = ecnt[t];
            zero_agg_kernel<<<(int)(((long)nd * 64 + 255) / 256), 256>>>((long)nd * 64);
            scatter_kernel<<<(e * 32 + 255) / 256, 256>>>(
                nullptr, 1, XOFF[s], edge[t], edge[t] + e, e, 1);
            agg_fin_kernel<<<(int)(((long)nd * 32 + 255) / 256), 256>>>(DEGOFF[t], nd);
            mma_sage<<<(nd + 63) / 64, 256, SMEM_SZ>>>(
                XOFF[d], whi + (long)(7 + t) * 131072, wlo + (long)(7 + t) * 131072,
                bvec + (long)(7 + t) * 256, nullptr, nullptr,
                xA + XOFF[d] * DIM, DEGOFF[t], nd, first[d] ? 0 : 1, 4, 4);
            first[d] = false;
        }
    }

    // ---------------- layer 2 (reads xA -> writes xB, dst reaction only) ------
    conv_x_kernel<<<(int)((100000L * 32 + 255) / 256), 256>>>(xA, 0, 100000L * 32, 1);
    for (int t = 0; t < 3; t++) {
        int s = ET_S[t];
        int nd = NNODE[0], e = ecnt[t];
        zero_agg_kernel<<<(int)(((long)nd * 64 + 255) / 256), 256>>>((long)nd * 64);
        scatter_kernel<<<(e * 32 + 255) / 256, 256>>>(
            nullptr, 0, XOFF[s], edge[t], edge[t] + e, e, 1);
        agg_fin_kernel<<<(int)(((long)nd * 32 + 255) / 256), 256>>>(DEGOFF[t], nd);
        mma_sage<<<(nd + 63) / 64, 256, SMEM_SZ>>>(
            XOFF[0], whi + (long)(14 + t) * 131072, wlo + (long)(14 + t) * 131072,
            bvec + (long)(14 + t) * 256, nullptr, nullptr,
            xB + XOFF[0] * DIM, DEGOFF[t], nd, t == 0 ? 0 : 1, 4, 4);
    }

    // head: relu(x_reaction, in xB) @ W_out + b_out
    final_gemm<<<(NNODE[0] + 63) / 64, 256>>>(1, XOFF[0], Wout, bout, (float*)d_out, NNODE[0]);
}

// round 8
// speedup vs baseline: 2.3834x; 1.0006x over previous
#include <cuda_runtime.h>
#include <cuda_bf16.h>
#include <cstdint>

// ---------------------------------------------------------------------------
// HeteroGNN (3-layer hetero SAGE) on GB300 — Round 6.
//   tcgen05 is unusable (harness PTX target is sm_103, not sm_103a).
//   SAGE GEMMs now use warp-level mma.sync bf16 (hi/lo split, 3 passes),
//   ldmatrix fragments, cp.async double-buffered K staging.
// ---------------------------------------------------------------------------

#define DIM 256

static const int  NNODE[4]  = {100000, 50000, 200000, 150000};
static const long XOFF[4]   = {0, 100000, 150000, 350000};
static const int  ET_S[7]   = {2, 3, 1, 2, 3, 0, 0};
static const int  ET_D[7]   = {0, 0, 0, 1, 1, 2, 3};
static const long DEGOFF[7] = {0, 100000, 200000, 300000, 350000, 400000, 600000};
#define DEG_TOTAL 750000

__device__ float g_xA[128000000];
__device__ float g_xB[128000000];
__device__ float g_agg[51200000];
__device__ float g_inv[DEG_TOTAL];
__device__ int   g_deg[DEG_TOTAL];
__device__ float g_r1[8 * 256];
__device__ float g_two[2 * 256];

__device__ __nv_bfloat16 g_Whi[21 * 256 * 512];  // [pair][N=256][K=512]
__device__ __nv_bfloat16 g_Wlo[21 * 256 * 512];
__device__ __nv_bfloat16 g_aggh[51200000];
__device__ __nv_bfloat16 g_aggl[51200000];
__device__ __nv_bfloat16 g_xh[128000000];
__device__ __nv_bfloat16 g_xl[128000000];

// ---- FFMA2 helpers (head GEMM) ---------------------------------------------
#define PACK2(out, lo, hi) \
    asm("mov.b64 %0, {%1, %2};" : "=l"(out) : "r"(__float_as_uint(lo)), "r"(__float_as_uint(hi)))
#define FMA2(acc, a, b) \
    asm("fma.rn.f32x2 %0, %1, %2, %0;" : "+l"(acc) : "l"(a), "l"(b))
#define UNPACK2(lo, hi, in) do { \
    unsigned _ul, _uh; \
    asm("mov.b64 {%0, %1}, %2;" : "=r"(_ul), "=r"(_uh) : "l"(in)); \
    lo = __uint_as_float(_ul); hi = __uint_as_float(_uh); } while (0)

__device__ __forceinline__ void red4(float* p, float4 v) {
    asm volatile("red.global.add.v4.f32 [%0], {%1,%2,%3,%4};"
                 :: "l"(p), "f"(v.x), "f"(v.y), "f"(v.z), "f"(v.w) : "memory");
}

// ---- mma.sync helpers (baseline PTX, works on plain sm_103 target) ----------
__device__ __forceinline__ uint32_t smem_u32(const void* p) {
    uint32_t a;
    asm("{ .reg .u64 t; cvta.to.shared.u64 t, %1; cvt.u32.u64 %0, t; }" : "=r"(a) : "l"(p));
    return a;
}
__device__ __forceinline__ void cp16(uint32_t dst, const void* src, int sz) {
    asm volatile("cp.async.cg.shared.global [%0], [%1], 16, %2;"
                 :: "r"(dst), "l"(src), "r"(sz) : "memory");
}
#define CP_COMMIT() asm volatile("cp.async.commit_group;" ::: "memory")
#define CP_WAIT(N)  asm volatile("cp.async.wait_group %0;" :: "n"(N) : "memory")

#define LDSM4(r0, r1, r2, r3, addr) \
    asm volatile("ldmatrix.sync.aligned.m8n8.x4.shared.b16 {%0,%1,%2,%3}, [%4];" \
                 : "=r"(r0), "=r"(r1), "=r"(r2), "=r"(r3) : "r"(addr))

#define MMA16816(c, a, b) \
    asm volatile("mma.sync.aligned.m16n8k16.row.col.f32.bf16.bf16.f32 " \
                 "{%0,%1,%2,%3}, {%4,%5,%6,%7}, {%8,%9}, {%0,%1,%2,%3};" \
                 : "+f"((c)[0]), "+f"((c)[1]), "+f"((c)[2]), "+f"((c)[3]) \
                 : "r"((a)[0]), "r"((a)[1]), "r"((a)[2]), "r"((a)[3]), \
                   "r"((b)[0]), "r"((b)[1]))

__device__ __forceinline__ const float* resolve_x(const float* ext, int sel, long rowoff) {
    if (sel == 0) return g_xA + rowoff * DIM;
    if (sel == 1) return g_xB + rowoff * DIM;
    return ext;
}
__device__ __forceinline__ void bsplit(float v, __nv_bfloat16& h, __nv_bfloat16& l) {
    h = __float2bfloat16(v);
    l = __float2bfloat16(v - __bfloat162float(h));
}

// ---- utility kernels ---------------------------------------------------------
__global__ void zero_deg_kernel() {
    int i = blockIdx.x * blockDim.x + threadIdx.x;
    if (i < DEG_TOTAL) g_deg[i] = 0;
}
__global__ void deg_kernel(const int* __restrict__ dstIdx, int e, long degOff) {
    int i = blockIdx.x * blockDim.x + threadIdx.x;
    if (i < e) atomicAdd(&g_deg[degOff + dstIdx[i]], 1);
}
__global__ void inv_kernel() {
    int i = blockIdx.x * blockDim.x + threadIdx.x;
    if (i < DEG_TOTAL) g_inv[i] = 1.0f / fmaxf((float)g_deg[i], 1.0f);
}
__global__ void zero_agg_kernel(long n4) {
    long i = (long)blockIdx.x * blockDim.x + threadIdx.x;
    if (i < n4) ((float4*)g_agg)[i] = make_float4(0.f, 0.f, 0.f, 0.f);
}
__global__ void rank1_kernel(const float* __restrict__ v, const float* __restrict__ W,
                             float* __restrict__ out) {
    int j = threadIdx.x;
    float acc = 0.f;
#pragma unroll 8
    for (int k = 0; k < 256; k++) acc += __ldg(&v[k]) * __ldg(&W[k * 256 + j]);
    out[j] = acc;
}
__global__ void t2_combine_kernel(const float* __restrict__ vl, const float* __restrict__ vr,
                                  const float* __restrict__ b) {
    __shared__ float red[2][8];
    int j = threadIdx.x;
    float a0 = vr[j] + b[j];
    float a1 = a0 + vl[j];
    float s0 = a0 * a0, s1 = a1 * a1;
#pragma unroll
    for (int o = 16; o > 0; o >>= 1) {
        s0 += __shfl_xor_sync(0xffffffffu, s0, o);
        s1 += __shfl_xor_sync(0xffffffffu, s1, o);
    }
    if ((j & 31) == 0) { red[0][j >> 5] = s0; red[1][j >> 5] = s1; }
    __syncthreads();
    float t0 = 0.f, t1 = 0.f;
#pragma unroll
    for (int w = 0; w < 8; w++) { t0 += red[0][w]; t1 += red[1][w]; }
    g_two[j]       = a0 * (1.0f / fmaxf(sqrtf(t0), 1e-12f));
    g_two[256 + j] = a1 * (1.0f / fmaxf(sqrtf(t1), 1e-12f));
}
__global__ void t2_apply_kernel(float* __restrict__ Out, long degoff, int n) {
    long i = (long)blockIdx.x * blockDim.x + threadIdx.x;
    long r = i >> 6;
    int c = (int)(i & 63);
    if (r >= n) return;
    int gate = g_deg[degoff + r] > 0 ? 1 : 0;
    float4 w = ((const float4*)(g_two + gate * 256))[c];
    float4 u = ((float4*)(Out + r * DIM))[c];
    u.x += w.x; u.y += w.y; u.z += w.z; u.w += w.w;
    ((float4*)(Out + r * DIM))[c] = u;
}

__global__ void scatter_kernel(const float* __restrict__ ext, int sel, long rowoff,
                               const int* __restrict__ srcIdx,
                               const int* __restrict__ dstIdx, int e, int relu) {
    int g = blockIdx.x * blockDim.x + threadIdx.x;
    int w = g >> 5;
    if (w >= e) return;
    int lane = g & 31;
    const float* X = resolve_x(ext, sel, rowoff);
    long s = srcIdx[w];
    long d = dstIdx[w];
    const float4* a = (const float4*)(X + s * DIM);
    float4 v0 = __ldg(&a[lane]);
    float4 v1 = __ldg(&a[lane + 32]);
    if (relu) {
        v0.x = fmaxf(v0.x, 0.f); v0.y = fmaxf(v0.y, 0.f);
        v0.z = fmaxf(v0.z, 0.f); v0.w = fmaxf(v0.w, 0.f);
        v1.x = fmaxf(v1.x, 0.f); v1.y = fmaxf(v1.y, 0.f);
        v1.z = fmaxf(v1.z, 0.f); v1.w = fmaxf(v1.w, 0.f);
    }
    float* o = g_agg + d * DIM;
    red4(o + lane * 4, v0);
    red4(o + 128 + lane * 4, v1);
}

// ---- conversion kernels -------------------------------------------------------
__global__ void conv_w_kernel(const float* __restrict__ Wl, const float* __restrict__ Wr) {
    long i = (long)blockIdx.x * blockDim.x + threadIdx.x;
    if (i >= 21L * 256 * 64) return;
    int p    = (int)(i / (256 * 64));
    int rem  = (int)(i % (256 * 64));
    int nrow = rem / 64;
    int k8   = (rem % 64) * 8;
    const float* base = ((k8 < 256) ? Wl : Wr) + (long)p * 65536;
    int kk = k8 & 255;
    __align__(16) __nv_bfloat16 h[8], l[8];
#pragma unroll
    for (int j = 0; j < 8; j++) {
        float v = __ldg(&base[(long)(kk + j) * 256 + nrow]);
        bsplit(v, h[j], l[j]);
    }
    long o = ((long)p * 256 + nrow) * 512 + k8;
    *(uint4*)(g_Whi + o) = *(const uint4*)h;
    *(uint4*)(g_Wlo + o) = *(const uint4*)l;
}

__global__ void conv_x_kernel(const float* __restrict__ src, long dstRow, long n8, int relu) {
    long i = (long)blockIdx.x * blockDim.x + threadIdx.x;
    if (i >= n8) return;
    float4 a = ((const float4*)src)[i * 2];
    float4 b = ((const float4*)src)[i * 2 + 1];
    if (relu) {
        a.x = fmaxf(a.x, 0.f); a.y = fmaxf(a.y, 0.f); a.z = fmaxf(a.z, 0.f); a.w = fmaxf(a.w, 0.f);
        b.x = fmaxf(b.x, 0.f); b.y = fmaxf(b.y, 0.f); b.z = fmaxf(b.z, 0.f); b.w = fmaxf(b.w, 0.f);
    }
    float v[8] = {a.x, a.y, a.z, a.w, b.x, b.y, b.z, b.w};
    __align__(16) __nv_bfloat16 h[8], l[8];
#pragma unroll
    for (int j = 0; j < 8; j++) bsplit(v[j], h[j], l[j]);
    *(uint4*)(g_xh + dstRow * 256 + i * 8) = *(const uint4*)h;
    *(uint4*)(g_xl + dstRow * 256 + i * 8) = *(const uint4*)l;
}

__global__ void agg_fin_kernel(long degoff, int n) {
    long i = (long)blockIdx.x * blockDim.x + threadIdx.x;
    if (i >= (long)n * 32) return;
    long row = i >> 5;
    float inv = g_inv[degoff + row];
    float4 a = ((const float4*)g_agg)[i * 2];
    float4 b = ((const float4*)g_agg)[i * 2 + 1];
    float v[8] = {a.x * inv, a.y * inv, a.z * inv, a.w * inv,
                  b.x * inv, b.y * inv, b.z * inv, b.w * inv};
    __align__(16) __nv_bfloat16 h[8], l[8];
#pragma unroll
    for (int j = 0; j < 8; j++) bsplit(v[j], h[j], l[j]);
    *(uint4*)(g_aggh + i * 8) = *(const uint4*)h;
    *(uint4*)(g_aggl + i * 8) = *(const uint4*)l;
}

// ---- mma.sync fused SAGE GEMM ------------------------------------------------
// C[64 x 256] = [agg_mean | relu(x)] (bf16 hi/lo) @ W (bf16 hi/lo), 3 passes,
// + bias + cvA + gate*cvG, row L2-norm, optional accumulate into Out.
// 8 warps: wm in {0,1} (rows), wn in {0..3} (cols); warp tile 32 x 64.
// SMEM: stages s in {0,1}: A[s][var][64][72] bf16, B[s][var][256][72] bf16.
#define A_STRIDE 144          // 72 bf16 per row
#define A_BLK    (64 * 144)   // 9216 B per (stage,var)
#define B_OFF    36864
#define B_BLK    (256 * 144)  // 36864 B per (stage,var)
#define CADD_OFF 184320
#define CVG_OFF  185344
#define RED_OFF  186368       // float[4][64]
#define SMEM_SZ  187392

__global__ __launch_bounds__(256, 1) void mma_sage(
    long xoff,
    const __nv_bfloat16* __restrict__ Wh, const __nv_bfloat16* __restrict__ Wlo_,
    const float* __restrict__ bias, const float* __restrict__ cvA,
    const float* __restrict__ cvG,
    float* __restrict__ Out, long degoff, int n, int accum, int nagg, int nx) {
    extern __shared__ char smem[];
    const int tid = threadIdx.x;
    const int lane = tid & 31, wid = tid >> 5;
    const int wm = wid >> 2, wn = wid & 3;
    const uint32_t sbase = smem_u32(smem);
    float* cadd   = (float*)(smem + CADD_OFF);
    float* cvgS   = (float*)(smem + CVG_OFF);
    float* rowred = (float*)(smem + RED_OFF);

    cadd[tid] = bias[tid] + (cvA ? cvA[tid] : 0.f);
    cvgS[tid] = cvG ? cvG[tid] : 0.f;

    const long row0 = (long)blockIdx.x * 64;
    const int nch = nagg + nx;

    float C[2][8][4];
#pragma unroll
    for (int mt = 0; mt < 2; mt++)
#pragma unroll
        for (int nt = 0; nt < 8; nt++)
#pragma unroll
            for (int q = 0; q < 4; q++) C[mt][nt][q] = 0.f;

    // producer mapping
    const int aslot = tid >> 1, avar = aslot >> 6, arow = aslot & 63;
    const int akh = (tid & 1) * 32;
    const long agrow = row0 + arow;
    const int asz = (agrow < n) ? 16 : 0;
    const long agc = (agrow < n) ? agrow : 0;

    auto issue = [&](int s, int c) {
        int kcol, wcol;
        const __nv_bfloat16 *Ah, *Al;
        if (c < nagg) { Ah = g_aggh; Al = g_aggl; kcol = c * 64; wcol = c * 64; }
        else {
            Ah = g_xh + xoff * 256; Al = g_xl + xoff * 256;
            kcol = (c - nagg) * 64; wcol = 256 + (c - nagg) * 64;
        }
        const __nv_bfloat16* asrc = (avar ? Al : Ah) + agc * 256 + kcol + akh;
        uint32_t adst = sbase + (uint32_t)(s * 2 + avar) * A_BLK + arow * A_STRIDE + akh * 2;
#pragma unroll
        for (int j = 0; j < 4; j++) cp16(adst + j * 16, asrc + j * 8, asz);
#pragma unroll
        for (int v = 0; v < 2; v++) {
            const __nv_bfloat16* b = (v ? Wlo_ : Wh) + (long)tid * 512 + wcol;
            uint32_t bdst = sbase + B_OFF + (uint32_t)(s * 2 + v) * B_BLK + tid * A_STRIDE;
#pragma unroll
            for (int j = 0; j < 8; j++) cp16(bdst + j * 16, b + j * 8, 16);
        }
        CP_COMMIT();
    };

    issue(0, 0);
    if (nch > 1) issue(1, 1);

    // ldmatrix lane addressing (constant per thread)
    const int a_r  = wm * 32 + (lane & 15);            // A row within block
    const int a_k8 = ((lane >> 4) & 1) * 8;            // A k sub-offset
    const int b_n  = ((lane >> 4) & 1) * 8 + (lane & 7);
    const int b_k8 = ((lane >> 3) & 1) * 8;

    for (int c = 0; c < nch; c++) {
        if (c + 1 < nch) { CP_WAIT(1); } else { CP_WAIT(0); }
        __syncthreads();
        const int s = c & 1;
        const uint32_t aBase = sbase + (uint32_t)(s * 2) * A_BLK;
        const uint32_t bBase = sbase + B_OFF + (uint32_t)(s * 2) * B_BLK;

#pragma unroll
        for (int k16 = 0; k16 < 4; k16++) {
            const int kb = k16 * 16;
            uint32_t ah[2][4], al[2][4], bh[8][2], bl[8][2];
#pragma unroll
            for (int mt = 0; mt < 2; mt++) {
                uint32_t ad = aBase + (a_r + mt * 16) * A_STRIDE + (kb + a_k8) * 2;
                LDSM4(ah[mt][0], ah[mt][1], ah[mt][2], ah[mt][3], ad);
                LDSM4(al[mt][0], al[mt][1], al[mt][2], al[mt][3], ad + A_BLK);
            }
#pragma unroll
            for (int np = 0; np < 4; np++) {
                uint32_t bd = bBase + (wn * 64 + np * 16 + b_n) * A_STRIDE + (kb + b_k8) * 2;
                LDSM4(bh[np*2][0], bh[np*2][1], bh[np*2+1][0], bh[np*2+1][1], bd);
                LDSM4(bl[np*2][0], bl[np*2][1], bl[np*2+1][0], bl[np*2+1][1], bd + B_BLK);
            }
#pragma unroll
            for (int mt = 0; mt < 2; mt++)
#pragma unroll
                for (int nt = 0; nt < 8; nt++) {
                    MMA16816(C[mt][nt], ah[mt], bh[nt]);
                    MMA16816(C[mt][nt], al[mt], bh[nt]);
                    MMA16816(C[mt][nt], ah[mt], bl[nt]);
                }
        }
        __syncthreads();
        if (c + 2 < nch) issue(s, c + 2);
    }

    // ---- epilogue ----
    // rows owned: for mt: r_lo = wm*32 + mt*16 + lane/4, r_hi = r_lo + 8
    float gate_lo[2], gate_hi[2];
#pragma unroll
    for (int mt = 0; mt < 2; mt++) {
        int rl = wm * 32 + mt * 16 + (lane >> 2);
        long grl = row0 + rl, grh = grl + 8;
        gate_lo[mt] = (cvG && grl < n) ? ((g_deg[degoff + grl] > 0) ? 1.f : 0.f) : 0.f;
        gate_hi[mt] = (cvG && grh < n) ? ((g_deg[degoff + grh] > 0) ? 1.f : 0.f) : 0.f;
    }
    float s_lo[2] = {0.f, 0.f}, s_hi[2] = {0.f, 0.f};
#pragma unroll
    for (int mt = 0; mt < 2; mt++)
#pragma unroll
        for (int nt = 0; nt < 8; nt++) {
            int col = wn * 64 + nt * 8 + (lane & 3) * 2;
            float c0 = cadd[col], c1 = cadd[col + 1];
            float g0 = cvgS[col], g1 = cvgS[col + 1];
            float v0 = C[mt][nt][0] + c0 + gate_lo[mt] * g0;
            float v1 = C[mt][nt][1] + c1 + gate_lo[mt] * g1;
            float v2 = C[mt][nt][2] + c0 + gate_hi[mt] * g0;
            float v3 = C[mt][nt][3] + c1 + gate_hi[mt] * g1;
            C[mt][nt][0] = v0; C[mt][nt][1] = v1; C[mt][nt][2] = v2; C[mt][nt][3] = v3;
            s_lo[mt] += v0 * v0 + v1 * v1;
            s_hi[mt] += v2 * v2 + v3 * v3;
        }
#pragma unroll
    for (int mt = 0; mt < 2; mt++) {
        s_lo[mt] += __shfl_xor_sync(0xffffffffu, s_lo[mt], 1);
        s_lo[mt] += __shfl_xor_sync(0xffffffffu, s_lo[mt], 2);
        s_hi[mt] += __shfl_xor_sync(0xffffffffu, s_hi[mt], 1);
        s_hi[mt] += __shfl_xor_sync(0xffffffffu, s_hi[mt], 2);
    }
    if ((lane & 3) == 0) {
#pragma unroll
        for (int mt = 0; mt < 2; mt++) {
            int rl = wm * 32 + mt * 16 + (lane >> 2);
            rowred[wn * 64 + rl]     = s_lo[mt];
            rowred[wn * 64 + rl + 8] = s_hi[mt];
        }
    }
    __syncthreads();
#pragma unroll
    for (int mt = 0; mt < 2; mt++) {
        int rl = wm * 32 + mt * 16 + (lane >> 2);
        int rh = rl + 8;
        float ssl = rowred[rl] + rowred[64 + rl] + rowred[128 + rl] + rowred[192 + rl];
        float ssh = rowred[rh] + rowred[64 + rh] + rowred[128 + rh] + rowred[192 + rh];
        float scl = 1.0f / fmaxf(sqrtf(ssl), 1e-12f);
        float sch = 1.0f / fmaxf(sqrtf(ssh), 1e-12f);
        long grl = row0 + rl, grh = row0 + rh;
#pragma unroll
        for (int nt = 0; nt < 8; nt++) {
            int col = wn * 64 + nt * 8 + (lane & 3) * 2;
            if (grl < n) {
                float2 o = make_float2(C[mt][nt][0] * scl, C[mt][nt][1] * scl);
                float* op = Out + grl * 256 + col;
                if (accum) { float2 u = *(const float2*)op; o.x += u.x; o.y += u.y; }
                *(float2*)op = o;
            }
            if (grh < n) {
                float2 o = make_float2(C[mt][nt][2] * sch, C[mt][nt][3] * sch);
                float* op = Out + grh * 256 + col;
                if (accum) { float2 u = *(const float2*)op; o.x += u.x; o.y += u.y; }
                *(float2*)op = o;
            }
        }
    }
}

// ---- final head: relu(x_reaction) @ W_out[256x128] + b_out -------------------
__global__ __launch_bounds__(256, 2) void final_gemm(
    int asel, long aoff, const float* __restrict__ W,
    const float* __restrict__ bias, float* __restrict__ C, int n) {
    __shared__ float As[16][64];
    __shared__ float Bs[16][128];
    const int tid = threadIdx.x;
    const long row0 = (long)blockIdx.x * 64;
    const int m = tid & 63, kq = tid >> 6;
    const int jb = tid & 31, kb2 = tid >> 5;
    const int tcol = tid & 31, tr = tid >> 5;

    const float* A = resolve_x(nullptr, asel, aoff);

    unsigned long long acc[8][2];
#pragma unroll
    for (int i = 0; i < 8; i++) { acc[i][0] = 0ULL; acc[i][1] = 0ULL; }

    const long arow = row0 + m;
    const bool aval = arow < n;

#pragma unroll 1
    for (int k0 = 0; k0 < 256; k0 += 16) {
        float4 av = make_float4(0.f, 0.f, 0.f, 0.f);
        if (aval) av = *(const float4*)&A[arow * DIM + k0 + kq * 4];
        av.x = fmaxf(av.x, 0.f); av.y = fmaxf(av.y, 0.f);
        av.z = fmaxf(av.z, 0.f); av.w = fmaxf(av.w, 0.f);
        float4 bv0 = *(const float4*)&W[(long)(k0 + kb2) * 128 + jb * 4];
        float4 bv1 = *(const float4*)&W[(long)(k0 + kb2 + 8) * 128 + jb * 4];
        __syncthreads();
        As[kq * 4 + 0][m] = av.x;
        As[kq * 4 + 1][m] = av.y;
        As[kq * 4 + 2][m] = av.z;
        As[kq * 4 + 3][m] = av.w;
        *(float4*)&Bs[kb2][jb * 4] = bv0;
        *(float4*)&Bs[kb2 + 8][jb * 4] = bv1;
        __syncthreads();
#pragma unroll
        for (int k = 0; k < 16; k++) {
            ulonglong2 b01 = *(const ulonglong2*)&Bs[k][tcol * 4];
            float4 a0 = *(const float4*)&As[k][tr * 8];
            float4 a1 = *(const float4*)&As[k][tr * 8 + 4];
            float aa[8] = {a0.x, a0.y, a0.z, a0.w, a1.x, a1.y, a1.z, a1.w};
#pragma unroll
            for (int i = 0; i < 8; i++) {
                unsigned long long a2v;
                PACK2(a2v, aa[i], aa[i]);
                FMA2(acc[i][0], a2v, b01.x);
                FMA2(acc[i][1], a2v, b01.y);
            }
        }
    }

    float4 bb = *(const float4*)&bias[tcol * 4];
    float bsv[4] = {bb.x, bb.y, bb.z, bb.w};
#pragma unroll
    for (int i = 0; i < 8; i++) {
        float v[4];
        UNPACK2(v[0], v[1], acc[i][0]);
        UNPACK2(v[2], v[3], acc[i][1]);
        long r = row0 + (long)tr * 8 + i;
        if (r < n) {
            float4 o0 = make_float4(v[0] + bsv[0], v[1] + bsv[1],
                                    v[2] + bsv[2], v[3] + bsv[3]);
            *(float4*)&C[r * 128 + tcol * 4] = o0;
        }
    }
}

// ---------------------------------------------------------------------------
extern "C" void kernel_launch(void* const* d_in, const int* in_sizes, int n_in,
                              void* d_out, int out_size) {
    const float* remb = (const float*)d_in[4];
    const float* cemb = (const float*)d_in[5];
    const float* ptab = (const float*)d_in[6];
    const float* mtab = (const float*)d_in[7];
    const float* Wl   = (const float*)d_in[8];
    const float* Wr   = (const float*)d_in[9];
    const float* bvec = (const float*)d_in[10];
    const float* Wout = (const float*)d_in[11];
    const float* bout = (const float*)d_in[12];
    const int* edge[7];
    int ecnt[7];
    for (int t = 0; t < 7; t++) {
        edge[t] = (const int*)d_in[13 + t];
        ecnt[t] = in_sizes[13 + t] / 2;
    }

    cudaFuncSetAttribute(mma_sage, cudaFuncAttributeMaxDynamicSharedMemorySize, SMEM_SZ);

    float *r1, *xA, *xB;
    __nv_bfloat16 *whi, *wlo;
    cudaGetSymbolAddress((void**)&r1, g_r1);
    cudaGetSymbolAddress((void**)&xA, g_xA);
    cudaGetSymbolAddress((void**)&xB, g_xB);
    cudaGetSymbolAddress((void**)&whi, g_Whi);
    cudaGetSymbolAddress((void**)&wlo, g_Wlo);

    // degrees -> inv
    zero_deg_kernel<<<(DEG_TOTAL + 255) / 256, 256>>>();
    for (int t = 0; t < 7; t++)
        deg_kernel<<<(ecnt[t] + 255) / 256, 256>>>(edge[t] + ecnt[t], ecnt[t], DEGOFF[t]);
    inv_kernel<<<(DEG_TOTAL + 255) / 256, 256>>>();

    // weight repack + layer-0 table conversion
    conv_w_kernel<<<(int)((21L * 256 * 64 + 255) / 256), 256>>>(Wl, Wr);
    conv_x_kernel<<<(int)((200000L * 32 + 255) / 256), 256>>>(ptab, XOFF[2], 200000L * 32, 0);
    conv_x_kernel<<<(int)((150000L * 32 + 255) / 256), 256>>>(mtab, XOFF[3], 150000L * 32, 0);

    // layer-0 rank-1 vectors
    rank1_kernel<<<1, 256>>>(remb, Wr + 0 * 65536L, r1 + 0 * 256);
    rank1_kernel<<<1, 256>>>(remb, Wr + 1 * 65536L, r1 + 1 * 256);
    rank1_kernel<<<1, 256>>>(cemb, Wl + 2 * 65536L, r1 + 2 * 256);
    rank1_kernel<<<1, 256>>>(remb, Wr + 2 * 65536L, r1 + 3 * 256);
    rank1_kernel<<<1, 256>>>(cemb, Wr + 3 * 65536L, r1 + 4 * 256);
    rank1_kernel<<<1, 256>>>(cemb, Wr + 4 * 65536L, r1 + 5 * 256);
    rank1_kernel<<<1, 256>>>(remb, Wl + 5 * 65536L, r1 + 6 * 256);
    rank1_kernel<<<1, 256>>>(remb, Wl + 6 * 65536L, r1 + 7 * 256);
    t2_combine_kernel<<<1, 256>>>(r1 + 2 * 256, r1 + 3 * 256, bvec + 2 * 256);

    const float* src_ext[2] = {ptab, mtab};

    // ---------------- layer 0 ----------------
    for (int t = 0; t < 2; t++) {     // dst reaction: agg GEMM + const
        int nd = NNODE[0], e = ecnt[t];
        zero_agg_kernel<<<(int)(((long)nd * 64 + 255) / 256), 256>>>((long)nd * 64);
        scatter_kernel<<<(e * 32 + 255) / 256, 256>>>(src_ext[t], 2, 0, edge[t], edge[t] + e, e, 0);
        agg_fin_kernel<<<(int)(((long)nd * 32 + 255) / 256), 256>>>(DEGOFF[t], nd);
        mma_sage<<<(nd + 63) / 64, 256, SMEM_SZ>>>(
            0, whi + (long)t * 131072, wlo + (long)t * 131072,
            bvec + (long)t * 256, r1 + t * 256, nullptr,
            xB + XOFF[0] * DIM, DEGOFF[t], nd, t == 0 ? 0 : 1, 4, 0);
    }
    t2_apply_kernel<<<(NNODE[0] * 64 + 255) / 256, 256>>>(xB + XOFF[0] * DIM, DEGOFF[2], NNODE[0]);
    for (int t = 3; t < 5; t++) {     // dst complex: agg GEMM + const
        int nd = NNODE[1], e = ecnt[t];
        zero_agg_kernel<<<(int)(((long)nd * 64 + 255) / 256), 256>>>((long)nd * 64);
        scatter_kernel<<<(e * 32 + 255) / 256, 256>>>(src_ext[t - 3], 2, 0, edge[t], edge[t] + e, e, 0);
        agg_fin_kernel<<<(int)(((long)nd * 32 + 255) / 256), 256>>>(DEGOFF[t], nd);
        mma_sage<<<(nd + 63) / 64, 256, SMEM_SZ>>>(
            0, whi + (long)t * 131072, wlo + (long)t * 131072,
            bvec + (long)t * 256, r1 + (t + 1) * 256, nullptr,
            xB + XOFF[1] * DIM, DEGOFF[t], nd, t == 3 ? 0 : 1, 4, 0);
    }
    // t5: gate*vl + ptab@Wr (x-phase only), dst protein
    mma_sage<<<(NNODE[2] + 63) / 64, 256, SMEM_SZ>>>(
        XOFF[2], whi + 5L * 131072, wlo + 5L * 131072,
        bvec + 5L * 256, nullptr, r1 + 6 * 256,
        xB + XOFF[2] * DIM, DEGOFF[5], NNODE[2], 0, 0, 4);
    // t6: gate*vl + mtab@Wr, dst molecule
    mma_sage<<<(NNODE[3] + 63) / 64, 256, SMEM_SZ>>>(
        XOFF[3], whi + 6L * 131072, wlo + 6L * 131072,
        bvec + 6L * 256, nullptr, r1 + 7 * 256,
        xB + XOFF[3] * DIM, DEGOFF[6], NNODE[3], 0, 0, 4);

    // ---------------- layer 1 (reads xB -> writes xA) ----------------
    conv_x_kernel<<<(int)((500000L * 32 + 255) / 256), 256>>>(xB, 0, 500000L * 32, 1);
    {
        bool first[4] = {true, true, true, true};
        for (int t = 0; t < 7; t++) {
            int s = ET_S[t], d = ET_D[t];
            int nd = NNODE[d], e = ecnt[t];
            zero_agg_kernel<<<(int)(((long)nd * 64 + 255) / 256), 256>>>((long)nd * 64);
            scatter_kernel<<<(e * 32 + 255) / 256, 256>>>(
                nullptr, 1, XOFF[s], edge[t], edge[t] + e, e, 1);
            agg_fin_kernel<<<(int)(((long)nd * 32 + 255) / 256), 256>>>(DEGOFF[t], nd);
            mma_sage<<<(nd + 63) / 64, 256, SMEM_SZ>>>(
                XOFF[d], whi + (long)(7 + t) * 131072, wlo + (long)(7 + t) * 131072,
                bvec + (long)(7 + t) * 256, nullptr, nullptr,
                xA + XOFF[d] * DIM, DEGOFF[t], nd, first[d] ? 0 : 1, 4, 4);
            first[d] = false;
        }
    }

    // ---------------- layer 2 (reads xA -> writes xB, dst reaction only) ------
    conv_x_kernel<<<(int)((100000L * 32 + 255) / 256), 256>>>(xA, 0, 100000L * 32, 1);
    for (int t = 0; t < 3; t++) {
        int s = ET_S[t];
        int nd = NNODE[0], e = ecnt[t];
        zero_agg_kernel<<<(int)(((long)nd * 64 + 255) / 256), 256>>>((long)nd * 64);
        scatter_kernel<<<(e * 32 + 255) / 256, 256>>>(
            nullptr, 0, XOFF[s], edge[t], edge[t] + e, e, 1);
        agg_fin_kernel<<<(int)(((long)nd * 32 + 255) / 256), 256>>>(DEGOFF[t], nd);
        mma_sage<<<(nd + 63) / 64, 256, SMEM_SZ>>>(
            XOFF[0], whi + (long)(14 + t) * 131072, wlo + (long)(14 + t) * 131072,
            bvec + (long)(14 + t) * 256, nullptr, nullptr,
            xB + XOFF[0] * DIM, DEGOFF[t], nd, t == 0 ? 0 : 1, 4, 4);
    }

    // head: relu(x_reaction, in xB) @ W_out + b_out
    final_gemm<<<(NNODE[0] + 63) / 64, 256>>>(1, XOFF[0], Wout, bout, (float*)d_out, NNODE[0]);
}